// round 1
// baseline (speedup 1.0000x reference)
#include <cuda_runtime.h>

// Problem constants
#define RR     128
#define LL     384
#define DDIM   128
#define HHEADS 8
#define DHEAD  64
#define DPAIR  128
#define INNERD 512
#define ML     (RR*LL)      // 49152 rows of the flattened (r,l) matrix
#define DHW    16           // head dim of PositionalWiseWeight

// ---------------- scratch (device globals; no allocation allowed) ----------
__device__ float g_Q [ML*INNERD];
__device__ float g_K [ML*INNERD];
__device__ float g_V [ML*INNERD];
__device__ float g_CW[ML*INNERD];
__device__ float g_CH[ML*INNERD];
__device__ float g_KS[ML*DDIM];
__device__ float g_QS[LL*DDIM];
__device__ float g_TIE [LL*HHEADS*RR];
__device__ float g_DOTS[HHEADS*LL*LL];
__device__ float g_PB  [LL*LL*HHEADS];
__device__ float g_ATT [HHEADS*LL*LL];

// ---------------------------------------------------------------------------
// Generic SGEMM: C[m][n] = alpha*(sum_k X[m][k]*W[k][n] + bias[n]) + beta*C
// BM=128, BN=64, BK=16, 256 threads, 8x4 per thread.
// Requires M%128==0, N%64==0, K%16==0, ld* %4==0 (all call sites satisfy).
// ---------------------------------------------------------------------------
__global__ __launch_bounds__(256) void sgemm_k(
    const float* __restrict__ X, int ldx,
    const float* __restrict__ W, int ldw,
    const float* __restrict__ bias,
    float* __restrict__ C, int ldc,
    int K, float alpha, float beta)
{
    __shared__ float As[16][132];   // [k][m], padded
    __shared__ float Bs[16][64];    // [k][n]
    const int t   = threadIdx.x;
    const int ti  = t >> 4;         // 0..15 -> rows ti*8..ti*8+7
    const int tj  = t & 15;         // 0..15 -> cols tj*4..tj*4+3
    const int row0 = blockIdx.y * 128;
    const int col0 = blockIdx.x * 64;

    float acc[8][4];
#pragma unroll
    for (int i = 0; i < 8; i++)
#pragma unroll
        for (int j = 0; j < 4; j++) acc[i][j] = 0.f;

    for (int k0 = 0; k0 < K; k0 += 16) {
        // A tile: 128 rows x 16 k = 512 float4, 2 per thread
#pragma unroll
        for (int it = 0; it < 2; it++) {
            int idx = t + it * 256;          // 0..511
            int mm  = idx >> 2;              // 0..127
            int kq  = (idx & 3) * 4;         // 0,4,8,12
            float4 v = *(const float4*)&X[(size_t)(row0 + mm) * ldx + k0 + kq];
            As[kq + 0][mm] = v.x; As[kq + 1][mm] = v.y;
            As[kq + 2][mm] = v.z; As[kq + 3][mm] = v.w;
        }
        // B tile: 16 k x 64 n = 256 float4, 1 per thread
        {
            int kk = t >> 4;                 // 0..15
            int nc = (t & 15) * 4;           // 0..60
            *(float4*)&Bs[kk][nc] =
                *(const float4*)&W[(size_t)(k0 + kk) * ldw + col0 + nc];
        }
        __syncthreads();
#pragma unroll
        for (int kk = 0; kk < 16; kk++) {
            float4 a0 = *(const float4*)&As[kk][ti * 8];
            float4 a1 = *(const float4*)&As[kk][ti * 8 + 4];
            float4 b4 = *(const float4*)&Bs[kk][tj * 4];
            float a[8] = {a0.x, a0.y, a0.z, a0.w, a1.x, a1.y, a1.z, a1.w};
            float b[4] = {b4.x, b4.y, b4.z, b4.w};
#pragma unroll
            for (int i = 0; i < 8; i++)
#pragma unroll
                for (int j = 0; j < 4; j++) acc[i][j] += a[i] * b[j];
        }
        __syncthreads();
    }

#pragma unroll
    for (int i = 0; i < 8; i++) {
        int mrow = row0 + ti * 8 + i;
#pragma unroll
        for (int j = 0; j < 4; j++) {
            int ncol = col0 + tj * 4 + j;
            float v = acc[i][j];
            if (bias) v += bias[ncol];
            v *= alpha;
            float* cp = &C[(size_t)mrow * ldc + ncol];
            if (beta != 0.f) v += beta * (*cp);
            *cp = v;
        }
    }
}

// ---------------------------------------------------------------------------
// Column ("width") attention: per (l,h) block, flash attention over R=128 rows
// Q,K,V layout: [(r*LL+l)*INNERD + h*DHEAD + d]. Output -> g_CW same layout.
// ---------------------------------------------------------------------------
__global__ __launch_bounds__(128) void col_attn_k(
    const float* __restrict__ Q, const float* __restrict__ K,
    const float* __restrict__ V, float* __restrict__ CW)
{
    const int l = blockIdx.x >> 3;
    const int h = blockIdx.x & 7;
    const int i = threadIdx.x;          // query row r

    __shared__ float Ks[64][64];
    __shared__ float Vs[64][64];

    float q[64];
    {
        const float* qp = &Q[((size_t)i * LL + l) * INNERD + h * DHEAD];
#pragma unroll
        for (int d = 0; d < 64; d += 4) {
            float4 v4 = *(const float4*)&qp[d];
            q[d] = v4.x; q[d + 1] = v4.y; q[d + 2] = v4.z; q[d + 3] = v4.w;
        }
    }

    float mx = -1e30f, lsum = 0.f, acc[64];
#pragma unroll
    for (int d = 0; d < 64; d++) acc[d] = 0.f;

    const int jr = i >> 1;              // row this thread loads (0..63)
    const int dh = (i & 1) * 32;        // which half of d

    for (int c = 0; c < 2; c++) {
        __syncthreads();
        const float* kp = &K[((size_t)(c * 64 + jr) * LL + l) * INNERD + h * DHEAD + dh];
        const float* vp = &V[((size_t)(c * 64 + jr) * LL + l) * INNERD + h * DHEAD + dh];
#pragma unroll
        for (int u = 0; u < 32; u += 4) {
            *(float4*)&Ks[jr][dh + u] = *(const float4*)&kp[u];
            *(float4*)&Vs[jr][dh + u] = *(const float4*)&vp[u];
        }
        __syncthreads();

        for (int j = 0; j < 64; j++) {
            float s = 0.f;
#pragma unroll
            for (int d = 0; d < 64; d++) s += q[d] * Ks[j][d];
            s *= 0.125f;
            float nm   = fmaxf(mx, s);
            float corr = __expf(mx - nm);
            float p    = __expf(s - nm);
            lsum = lsum * corr + p;
#pragma unroll
            for (int d = 0; d < 64; d++) acc[d] = acc[d] * corr + p * Vs[j][d];
            mx = nm;
        }
    }

    float inv = 1.f / lsum;
    float* op = &CW[((size_t)i * LL + l) * INNERD + h * DHEAD];
#pragma unroll
    for (int d = 0; d < 64; d += 4) {
        float4 o = {acc[d] * inv, acc[d + 1] * inv, acc[d + 2] * inv, acc[d + 3] * inv};
        *(float4*)&op[d] = o;
    }
}

// ---------------------------------------------------------------------------
// Row-tie weights: w_tie[l,h,r] = softmax_r( <qs[l,h,:], ks[r,l,h,:]> / 4 )
// ---------------------------------------------------------------------------
__global__ __launch_bounds__(128) void tie_k(
    const float* __restrict__ QS, const float* __restrict__ KS,
    float* __restrict__ TIE)
{
    const int l = blockIdx.x >> 3;
    const int h = blockIdx.x & 7;
    const int r = threadIdx.x;
    const float* q = &QS[l * DDIM + h * DHW];
    const float* k = &KS[((size_t)r * LL + l) * DDIM + h * DHW];
    float s = 0.f;
#pragma unroll
    for (int d = 0; d < DHW; d++) s += q[d] * k[d];
    s *= 0.25f;

    __shared__ float red[128];
    red[r] = s; __syncthreads();
    for (int o = 64; o; o >>= 1) { if (r < o) red[r] = fmaxf(red[r], red[r + o]); __syncthreads(); }
    float m = red[0]; __syncthreads();
    float e = __expf(s - m);
    red[r] = e; __syncthreads();
    for (int o = 64; o; o >>= 1) { if (r < o) red[r] += red[r + o]; __syncthreads(); }
    TIE[(l * HHEADS + h) * RR + r] = e / red[0];
}

// ---------------------------------------------------------------------------
// dots_h[h,i,j] = 0.125 * sum_r sum_d  w_tie[i,h,r]*QH[r,i,h,d]*KH[r,j,h,d]
// Per-head GEMM with K = R*DH = 8192; 32x32 tile per block, 2x2 per thread.
// ---------------------------------------------------------------------------
__global__ __launch_bounds__(256) void dots_k(
    const float* __restrict__ TIE, const float* __restrict__ QH,
    const float* __restrict__ KH, float* __restrict__ DOTS)
{
    const int h  = blockIdx.z;
    const int i0 = blockIdx.y * 32;
    const int j0 = blockIdx.x * 32;
    const int t  = threadIdx.x;
    const int ti = t >> 4, tj = t & 15;
    const int li = t >> 3;              // 0..31 row within tile (for loads)
    const int d0 = (t & 7) * 8;         // 0..56

    __shared__ float As[64][33];        // [d][i]
    __shared__ float Bs[64][33];        // [d][j]
    float acc00 = 0, acc01 = 0, acc10 = 0, acc11 = 0;

    for (int r = 0; r < RR; r++) {
        float wv = TIE[((i0 + li) * HHEADS + h) * RR + r];
        const float* qp = &QH[((size_t)r * LL + (i0 + li)) * INNERD + h * DHEAD + d0];
        const float* kp = &KH[((size_t)r * LL + (j0 + li)) * INNERD + h * DHEAD + d0];
#pragma unroll
        for (int u = 0; u < 8; u++) {
            As[d0 + u][li] = wv * qp[u];
            Bs[d0 + u][li] = kp[u];
        }
        __syncthreads();
#pragma unroll
        for (int d = 0; d < 64; d++) {
            float a0 = As[d][ti * 2], a1 = As[d][ti * 2 + 1];
            float b0 = Bs[d][tj * 2], b1 = Bs[d][tj * 2 + 1];
            acc00 += a0 * b0; acc01 += a0 * b1;
            acc10 += a1 * b0; acc11 += a1 * b1;
        }
        __syncthreads();
    }
    float* dp = &DOTS[(size_t)h * LL * LL];
    dp[(i0 + ti * 2 + 0) * LL + (j0 + tj * 2 + 0)] = acc00 * 0.125f;
    dp[(i0 + ti * 2 + 0) * LL + (j0 + tj * 2 + 1)] = acc01 * 0.125f;
    dp[(i0 + ti * 2 + 1) * LL + (j0 + tj * 2 + 0)] = acc10 * 0.125f;
    dp[(i0 + ti * 2 + 1) * LL + (j0 + tj * 2 + 1)] = acc11 * 0.125f;
}

// ---------------------------------------------------------------------------
// Pair bias: PB[(i*L+j)*H + h] = LN(pair[i,j,:]) @ Wpair[:,h]
// One warp per (i,j).
// ---------------------------------------------------------------------------
__global__ __launch_bounds__(128) void pb_k(
    const float* __restrict__ pair, const float* __restrict__ gam,
    const float* __restrict__ bet, const float* __restrict__ Wp,
    float* __restrict__ PB)
{
    const int w    = threadIdx.x >> 5;
    const int lane = threadIdx.x & 31;
    const int pid  = blockIdx.x * 4 + w;      // < L*L
    float4 x4 = *(const float4*)&pair[(size_t)pid * DPAIR + lane * 4];
    float x[4] = {x4.x, x4.y, x4.z, x4.w};
    float s1 = x[0] + x[1] + x[2] + x[3];
    float s2 = x[0]*x[0] + x[1]*x[1] + x[2]*x[2] + x[3]*x[3];
#pragma unroll
    for (int o = 16; o; o >>= 1) {
        s1 += __shfl_xor_sync(0xffffffffu, s1, o);
        s2 += __shfl_xor_sync(0xffffffffu, s2, o);
    }
    float mu  = s1 * (1.f / DPAIR);
    float var = s2 * (1.f / DPAIR) - mu * mu;
    float inv = rsqrtf(var + 1e-5f);

    float acc[8];
#pragma unroll
    for (int hh = 0; hh < 8; hh++) acc[hh] = 0.f;
#pragma unroll
    for (int u = 0; u < 4; u++) {
        int c = lane * 4 + u;
        float nx = (x[u] - mu) * inv * gam[c] + bet[c];
#pragma unroll
        for (int hh = 0; hh < 8; hh++) acc[hh] += nx * Wp[c * 8 + hh];
    }
#pragma unroll
    for (int o = 16; o; o >>= 1)
#pragma unroll
        for (int hh = 0; hh < 8; hh++) acc[hh] += __shfl_xor_sync(0xffffffffu, acc[hh], o);
    if (lane == 0) {
#pragma unroll
        for (int hh = 0; hh < 8; hh++) PB[(size_t)pid * 8 + hh] = acc[hh];
    }
}

// ---------------------------------------------------------------------------
// attn_h = softmax_j( dots[h,i,j] + PB[i,j,h] )
// ---------------------------------------------------------------------------
__global__ __launch_bounds__(128) void softh_k(
    const float* __restrict__ DOTS, const float* __restrict__ PB,
    float* __restrict__ ATT)
{
    const int i = blockIdx.x;
    const int h = blockIdx.y;
    const int t = threadIdx.x;
    const float* dp = &DOTS[((size_t)h * LL + i) * LL];
    float x[3];
#pragma unroll
    for (int u = 0; u < 3; u++) {
        int j = t + u * 128;
        x[u] = dp[j] + PB[((size_t)i * LL + j) * 8 + h];
    }
    __shared__ float red[128];
    float lm = fmaxf(fmaxf(x[0], x[1]), x[2]);
    red[t] = lm; __syncthreads();
    for (int o = 64; o; o >>= 1) { if (t < o) red[t] = fmaxf(red[t], red[t + o]); __syncthreads(); }
    float mx = red[0]; __syncthreads();
    float e[3], ls = 0.f;
#pragma unroll
    for (int u = 0; u < 3; u++) { e[u] = __expf(x[u] - mx); ls += e[u]; }
    red[t] = ls; __syncthreads();
    for (int o = 64; o; o >>= 1) { if (t < o) red[t] += red[t + o]; __syncthreads(); }
    float inv = 1.f / red[0];
    float* ap = &ATT[((size_t)h * LL + i) * LL];
#pragma unroll
    for (int u = 0; u < 3; u++) ap[t + u * 128] = e[u] * inv;
}

// ---------------------------------------------------------------------------
// oh[r,h,i,d] = sum_j attn[h,i,j] * VH[r,j,h,d]   -> CH[(r*L+i)*512 + h*64 + d]
// Block: (r,h) x 32-i-tile, 32x64 output, 2x4 per thread, loop over j tiles.
// ---------------------------------------------------------------------------
__global__ __launch_bounds__(256) void oh_k(
    const float* __restrict__ ATT, const float* __restrict__ VH,
    float* __restrict__ CH)
{
    const int r  = blockIdx.y >> 3;
    const int h  = blockIdx.y & 7;
    const int i0 = blockIdx.x * 32;
    const int t  = threadIdx.x;
    const int ti = t >> 4, tj = t & 15;     // 2 i's, 4 d's per thread
    const int li = t >> 3;                   // 0..31 (load row)
    const int j4 = (t & 7) * 4;              // ATT load col
    const int d0 = (t & 7) * 8;              // V load col

    __shared__ float Ats[32][36];
    __shared__ float Vs [32][68];
    float acc[2][4];
#pragma unroll
    for (int a = 0; a < 2; a++)
#pragma unroll
        for (int b = 0; b < 4; b++) acc[a][b] = 0.f;

    const float* arow = &ATT[((size_t)h * LL + (i0 + li)) * LL];

    for (int jt = 0; jt < LL; jt += 32) {
        *(float4*)&Ats[li][j4] = *(const float4*)&arow[jt + j4];
        const float* vp = &VH[((size_t)r * LL + (jt + li)) * INNERD + h * DHEAD + d0];
        *(float4*)&Vs[li][d0]     = *(const float4*)&vp[0];
        *(float4*)&Vs[li][d0 + 4] = *(const float4*)&vp[4];
        __syncthreads();
#pragma unroll
        for (int jj = 0; jj < 32; jj++) {
            float a0 = Ats[ti * 2][jj], a1 = Ats[ti * 2 + 1][jj];
            float4 b4 = *(const float4*)&Vs[jj][tj * 4];
            acc[0][0] += a0 * b4.x; acc[0][1] += a0 * b4.y;
            acc[0][2] += a0 * b4.z; acc[0][3] += a0 * b4.w;
            acc[1][0] += a1 * b4.x; acc[1][1] += a1 * b4.y;
            acc[1][2] += a1 * b4.z; acc[1][3] += a1 * b4.w;
        }
        __syncthreads();
    }
#pragma unroll
    for (int a = 0; a < 2; a++) {
        float* op = &CH[((size_t)r * LL + (i0 + ti * 2 + a)) * INNERD + h * DHEAD + tj * 4];
        float4 o = {acc[a][0], acc[a][1], acc[a][2], acc[a][3]};
        *(float4*)op = o;
    }
}

// ---------------------------------------------------------------------------
// Host launch
// ---------------------------------------------------------------------------
static float* sym(const void* s) {
    void* p = nullptr;
    cudaGetSymbolAddress(&p, s);
    return (float*)p;
}

extern "C" void kernel_launch(void* const* d_in, const int* in_sizes, int n_in,
                              void* d_out, int out_size)
{
    const float* m     = (const float*)d_in[0];
    const float* pair  = (const float*)d_in[1];
    const float* Wq_w  = (const float*)d_in[2];
    const float* Wkv_w = (const float*)d_in[3];
    const float* Wo_w  = (const float*)d_in[4];
    const float* bo_w  = (const float*)d_in[5];
    const float* Wq_h  = (const float*)d_in[6];
    const float* Wkv_h = (const float*)d_in[7];
    const float* Wo_h  = (const float*)d_in[8];
    const float* bo_h  = (const float*)d_in[9];
    const float* ln_g  = (const float*)d_in[10];
    const float* ln_b  = (const float*)d_in[11];
    const float* Wpair = (const float*)d_in[12];
    const float* Wsq   = (const float*)d_in[13];
    const float* bsq   = (const float*)d_in[14];
    const float* Wsk   = (const float*)d_in[15];
    const float* bsk   = (const float*)d_in[16];
    float* out = (float*)d_out;

    float* Q    = sym(g_Q);
    float* K    = sym(g_K);
    float* V    = sym(g_V);
    float* CW   = sym(g_CW);
    float* CH   = sym(g_CH);
    float* KS   = sym(g_KS);
    float* QS   = sym(g_QS);
    float* TIE  = sym(g_TIE);
    float* DOTS = sym(g_DOTS);
    float* PB   = sym(g_PB);
    float* ATT  = sym(g_ATT);

    const dim3 gBig(8, 384);    // N=512, M=49152
    const dim3 gD  (2, 384);    // N=128, M=49152

    // ---- width (column) attention ----
    sgemm_k<<<gBig, 256>>>(m, DDIM, Wq_w,        INNERD,     nullptr, Q, INNERD, DDIM, 1.f, 0.f);
    sgemm_k<<<gBig, 256>>>(m, DDIM, Wkv_w,       2 * INNERD, nullptr, K, INNERD, DDIM, 1.f, 0.f);
    sgemm_k<<<gBig, 256>>>(m, DDIM, Wkv_w + 512, 2 * INNERD, nullptr, V, INNERD, DDIM, 1.f, 0.f);
    col_attn_k<<<LL * HHEADS, 128>>>(Q, K, V, CW);

    // ---- height (row) attention ----
    sgemm_k<<<gBig, 256>>>(m, DDIM, Wq_h,        INNERD,     nullptr, Q, INNERD, DDIM, 1.f, 0.f);
    sgemm_k<<<gBig, 256>>>(m, DDIM, Wkv_h,       2 * INNERD, nullptr, K, INNERD, DDIM, 1.f, 0.f);
    sgemm_k<<<gBig, 256>>>(m, DDIM, Wkv_h + 512, 2 * INNERD, nullptr, V, INNERD, DDIM, 1.f, 0.f);

    sgemm_k<<<dim3(2, 3), 256>>>(m, DDIM, Wsq, DDIM, bsq, QS, DDIM, DDIM, 1.f, 0.f);  // M=384
    sgemm_k<<<gD, 256>>>(m, DDIM, Wsk, DDIM, bsk, KS, DDIM, DDIM, 1.f, 0.f);

    tie_k<<<LL * HHEADS, 128>>>(QS, KS, TIE);
    dots_k<<<dim3(12, 12, HHEADS), 256>>>(TIE, Q, K, DOTS);
    pb_k<<<LL * LL / 4, 128>>>(pair, ln_g, ln_b, Wpair, PB);
    softh_k<<<dim3(LL, HHEADS), 128>>>(DOTS, PB, ATT);
    oh_k<<<dim3(12, RR * HHEADS), 256>>>(ATT, V, CH);

    // ---- fused output: out = 0.5*(CW@Wo_w + bo_w) + 0.5*(CH@Wo_h + bo_h) ----
    sgemm_k<<<gD, 256>>>(CW, INNERD, Wo_w, DDIM, bo_w, out, DDIM, INNERD, 0.5f, 0.f);
    sgemm_k<<<gD, 256>>>(CH, INNERD, Wo_h, DDIM, bo_h, out, DDIM, INNERD, 0.5f, 1.f);
}

// round 3
// speedup vs baseline: 1.1327x; 1.1327x over previous
#include <cuda_runtime.h>
#include <cstdint>

// Problem constants
#define RR     128
#define LL     384
#define DDIM   128
#define HHEADS 8
#define DHEAD  64
#define DPAIR  128
#define INNERD 512
#define ML     (RR*LL)
#define DHW    16

// ---------------- scratch (device globals; no allocation allowed) ----------
__device__ float g_Q [ML*INNERD];
__device__ float g_K [ML*INNERD];
__device__ float g_V [ML*INNERD];
__device__ float g_CW[ML*INNERD];
__device__ float g_CH[ML*INNERD];
__device__ float g_KS[ML*DDIM];
__device__ float g_QS[LL*DDIM];
__device__ float g_TIE [LL*HHEADS*RR];
__device__ float g_DOTS[HHEADS*LL*LL];
__device__ float g_PB  [LL*LL*HHEADS];
__device__ float g_ATT [HHEADS*LL*LL];
// transposed weights (K-major, [N][K])
__device__ float g_WtQw [INNERD*DDIM];
__device__ float g_WtKVw[2*INNERD*DDIM];
__device__ float g_WtOw [DDIM*INNERD];
__device__ float g_WtQh [INNERD*DDIM];
__device__ float g_WtKVh[2*INNERD*DDIM];
__device__ float g_WtOh [DDIM*INNERD];
__device__ float g_WtSq [DDIM*DDIM];
__device__ float g_WtSk [DDIM*DDIM];

// ---------------------------------------------------------------------------
// tf32 warp MMA: D(16x8) += A(16x8,row) * B(8x8,col)
// ---------------------------------------------------------------------------
__device__ __forceinline__ void mma_tf32(float* d, const uint32_t* a, const uint32_t* b) {
    asm volatile(
        "mma.sync.aligned.m16n8k8.row.col.f32.tf32.tf32.f32 "
        "{%0,%1,%2,%3}, {%4,%5,%6,%7}, {%8,%9}, {%0,%1,%2,%3};"
        : "+f"(d[0]), "+f"(d[1]), "+f"(d[2]), "+f"(d[3])
        : "r"(a[0]), "r"(a[1]), "r"(a[2]), "r"(a[3]), "r"(b[0]), "r"(b[1]));
}
__device__ __forceinline__ uint32_t f2tf32(float v) {
    uint32_t o;
    asm("cvt.rna.tf32.f32 %0, %1;" : "=r"(o) : "f"(v));
    return o;
}

// ---------------------------------------------------------------------------
// Weight transpose: Wt[n*K + k] = W[k*N + n].  grid (N/32, K/32), block (32,8)
// ---------------------------------------------------------------------------
__global__ void transpose_k(const float* __restrict__ W, float* __restrict__ Wt,
                            int K, int N)
{
    __shared__ float tile[32][33];
    int kb = blockIdx.y * 32, nb = blockIdx.x * 32;
    int tx = threadIdx.x, ty = threadIdx.y;
#pragma unroll
    for (int i = 0; i < 32; i += 8)
        tile[ty + i][tx] = W[(size_t)(kb + ty + i) * N + nb + tx];
    __syncthreads();
#pragma unroll
    for (int i = 0; i < 32; i += 8)
        Wt[(size_t)(nb + ty + i) * K + kb + tx] = tile[tx][ty + i];
}

// ---------------------------------------------------------------------------
// tf32 tensor-core GEMM:
//   C[m][n] = alpha*(sum_k X[m][k]*Wt[n][k] + bias[n]) + beta*C
// Block 128x128, BK=16, 256 threads = 8 warps (4 rows x 2 cols), warp 32x64.
// ---------------------------------------------------------------------------
__global__ __launch_bounds__(256) void gemm_tc(
    const float* __restrict__ X, int ldx,
    const float* __restrict__ Wt,          // [N][K] K-major
    const float* __restrict__ bias,
    float* __restrict__ C, int ldc,
    int K, float alpha, float beta)
{
    __shared__ float As[128 * 20];   // [m][k], stride 20 (conflict-free frags)
    __shared__ float Bs[128 * 20];   // [n][k]

    const int t    = threadIdx.x;
    const int lane = t & 31;
    const int wid  = t >> 5;
    const int wm   = (wid & 3) * 32;     // warp row offset in tile
    const int wn   = (wid >> 2) * 64;    // warp col offset in tile
    const int row0 = blockIdx.y * 128;
    const int col0 = blockIdx.x * 128;

    float acc[2][8][4];
#pragma unroll
    for (int mt = 0; mt < 2; mt++)
#pragma unroll
        for (int nt = 0; nt < 8; nt++)
#pragma unroll
            for (int i = 0; i < 4; i++) acc[mt][nt][i] = 0.f;

    const int lr = t >> 2;          // 0..63 load row
    const int lc = (t & 3) * 4;     // 0,4,8,12 load k

    for (int k0 = 0; k0 < K; k0 += 16) {
#pragma unroll
        for (int half = 0; half < 2; half++) {
            int r = lr + half * 64;
            float4 va = *(const float4*)&X [(size_t)(row0 + r) * ldx + k0 + lc];
            float4 vb = *(const float4*)&Wt[(size_t)(col0 + r) * K   + k0 + lc];
            uint4 ua, ub;
            ua.x = f2tf32(va.x); ua.y = f2tf32(va.y);
            ua.z = f2tf32(va.z); ua.w = f2tf32(va.w);
            ub.x = f2tf32(vb.x); ub.y = f2tf32(vb.y);
            ub.z = f2tf32(vb.z); ub.w = f2tf32(vb.w);
            *(uint4*)&As[r * 20 + lc] = ua;
            *(uint4*)&Bs[r * 20 + lc] = ub;
        }
        __syncthreads();
#pragma unroll
        for (int ks = 0; ks < 16; ks += 8) {
            uint32_t af[2][4];
            const int fr = lane >> 2;      // 0..7
            const int fc = ks + (lane & 3);
#pragma unroll
            for (int mt = 0; mt < 2; mt++) {
                int r = wm + mt * 16 + fr;
                af[mt][0] = __float_as_uint(As[r * 20 + fc]);
                af[mt][1] = __float_as_uint(As[(r + 8) * 20 + fc]);
                af[mt][2] = __float_as_uint(As[r * 20 + fc + 4]);
                af[mt][3] = __float_as_uint(As[(r + 8) * 20 + fc + 4]);
            }
#pragma unroll
            for (int nt = 0; nt < 8; nt++) {
                uint32_t bf[2];
                int n = wn + nt * 8 + fr;
                bf[0] = __float_as_uint(Bs[n * 20 + fc]);
                bf[1] = __float_as_uint(Bs[n * 20 + fc + 4]);
                mma_tf32(acc[0][nt], af[0], bf);
                mma_tf32(acc[1][nt], af[1], bf);
            }
        }
        __syncthreads();
    }

    // ---- epilogue ----
#pragma unroll
    for (int mt = 0; mt < 2; mt++) {
#pragma unroll
        for (int nt = 0; nt < 8; nt++) {
            int rg = row0 + wm + mt * 16 + (lane >> 2);
            int cg = col0 + wn + nt * 8 + (lane & 3) * 2;
            float bx = 0.f, by = 0.f;
            if (bias) { bx = bias[cg]; by = bias[cg + 1]; }
#pragma unroll
            for (int half = 0; half < 2; half++) {
                int r = rg + half * 8;
                float vx = alpha * (acc[mt][nt][half * 2 + 0] + bx);
                float vy = alpha * (acc[mt][nt][half * 2 + 1] + by);
                float2* cp = (float2*)&C[(size_t)r * ldc + cg];
                if (beta != 0.f) {
                    float2 o = *cp;
                    vx += beta * o.x; vy += beta * o.y;
                }
                float2 v = {vx, vy};
                *cp = v;
            }
        }
    }
}

// ---------------------------------------------------------------------------
// Column ("width") attention (unchanged)
// ---------------------------------------------------------------------------
__global__ __launch_bounds__(128) void col_attn_k(
    const float* __restrict__ Q, const float* __restrict__ K,
    const float* __restrict__ V, float* __restrict__ CW)
{
    const int l = blockIdx.x >> 3;
    const int h = blockIdx.x & 7;
    const int i = threadIdx.x;

    __shared__ float Ks[64][64];
    __shared__ float Vs[64][64];

    float q[64];
    {
        const float* qp = &Q[((size_t)i * LL + l) * INNERD + h * DHEAD];
#pragma unroll
        for (int d = 0; d < 64; d += 4) {
            float4 v4 = *(const float4*)&qp[d];
            q[d] = v4.x; q[d + 1] = v4.y; q[d + 2] = v4.z; q[d + 3] = v4.w;
        }
    }

    float mx = -1e30f, lsum = 0.f, acc[64];
#pragma unroll
    for (int d = 0; d < 64; d++) acc[d] = 0.f;

    const int jr = i >> 1;
    const int dh = (i & 1) * 32;

    for (int c = 0; c < 2; c++) {
        __syncthreads();
        const float* kp = &K[((size_t)(c * 64 + jr) * LL + l) * INNERD + h * DHEAD + dh];
        const float* vp = &V[((size_t)(c * 64 + jr) * LL + l) * INNERD + h * DHEAD + dh];
#pragma unroll
        for (int u = 0; u < 32; u += 4) {
            *(float4*)&Ks[jr][dh + u] = *(const float4*)&kp[u];
            *(float4*)&Vs[jr][dh + u] = *(const float4*)&vp[u];
        }
        __syncthreads();

        for (int j = 0; j < 64; j++) {
            float s = 0.f;
#pragma unroll
            for (int d = 0; d < 64; d++) s += q[d] * Ks[j][d];
            s *= 0.125f;
            float nm   = fmaxf(mx, s);
            float corr = __expf(mx - nm);
            float p    = __expf(s - nm);
            lsum = lsum * corr + p;
#pragma unroll
            for (int d = 0; d < 64; d++) acc[d] = acc[d] * corr + p * Vs[j][d];
            mx = nm;
        }
    }

    float inv = 1.f / lsum;
    float* op = &CW[((size_t)i * LL + l) * INNERD + h * DHEAD];
#pragma unroll
    for (int d = 0; d < 64; d += 4) {
        float4 o = {acc[d] * inv, acc[d + 1] * inv, acc[d + 2] * inv, acc[d + 3] * inv};
        *(float4*)&op[d] = o;
    }
}

// ---------------------------------------------------------------------------
// Row-tie weights (unchanged)
// ---------------------------------------------------------------------------
__global__ __launch_bounds__(128) void tie_k(
    const float* __restrict__ QS, const float* __restrict__ KS,
    float* __restrict__ TIE)
{
    const int l = blockIdx.x >> 3;
    const int h = blockIdx.x & 7;
    const int r = threadIdx.x;
    const float* q = &QS[l * DDIM + h * DHW];
    const float* k = &KS[((size_t)r * LL + l) * DDIM + h * DHW];
    float s = 0.f;
#pragma unroll
    for (int d = 0; d < DHW; d++) s += q[d] * k[d];
    s *= 0.25f;

    __shared__ float red[128];
    red[r] = s; __syncthreads();
    for (int o = 64; o; o >>= 1) { if (r < o) red[r] = fmaxf(red[r], red[r + o]); __syncthreads(); }
    float m = red[0]; __syncthreads();
    float e = __expf(s - m);
    red[r] = e; __syncthreads();
    for (int o = 64; o; o >>= 1) { if (r < o) red[r] += red[r + o]; __syncthreads(); }
    TIE[(l * HHEADS + h) * RR + r] = e / red[0];
}

// ---------------------------------------------------------------------------
// dots_h (unchanged this round)
// ---------------------------------------------------------------------------
__global__ __launch_bounds__(256) void dots_k(
    const float* __restrict__ TIE, const float* __restrict__ QH,
    const float* __restrict__ KH, float* __restrict__ DOTS)
{
    const int h  = blockIdx.z;
    const int i0 = blockIdx.y * 32;
    const int j0 = blockIdx.x * 32;
    const int t  = threadIdx.x;
    const int ti = t >> 4, tj = t & 15;
    const int li = t >> 3;
    const int d0 = (t & 7) * 8;

    __shared__ float As[64][33];
    __shared__ float Bs[64][33];
    float acc00 = 0, acc01 = 0, acc10 = 0, acc11 = 0;

    for (int r = 0; r < RR; r++) {
        float wv = TIE[((i0 + li) * HHEADS + h) * RR + r];
        const float* qp = &QH[((size_t)r * LL + (i0 + li)) * INNERD + h * DHEAD + d0];
        const float* kp = &KH[((size_t)r * LL + (j0 + li)) * INNERD + h * DHEAD + d0];
#pragma unroll
        for (int u = 0; u < 8; u++) {
            As[d0 + u][li] = wv * qp[u];
            Bs[d0 + u][li] = kp[u];
        }
        __syncthreads();
#pragma unroll
        for (int d = 0; d < 64; d++) {
            float a0 = As[d][ti * 2], a1 = As[d][ti * 2 + 1];
            float b0 = Bs[d][tj * 2], b1 = Bs[d][tj * 2 + 1];
            acc00 += a0 * b0; acc01 += a0 * b1;
            acc10 += a1 * b0; acc11 += a1 * b1;
        }
        __syncthreads();
    }
    float* dp = &DOTS[(size_t)h * LL * LL];
    dp[(i0 + ti * 2 + 0) * LL + (j0 + tj * 2 + 0)] = acc00 * 0.125f;
    dp[(i0 + ti * 2 + 0) * LL + (j0 + tj * 2 + 1)] = acc01 * 0.125f;
    dp[(i0 + ti * 2 + 1) * LL + (j0 + tj * 2 + 0)] = acc10 * 0.125f;
    dp[(i0 + ti * 2 + 1) * LL + (j0 + tj * 2 + 1)] = acc11 * 0.125f;
}

// ---------------------------------------------------------------------------
// Pair bias (unchanged)
// ---------------------------------------------------------------------------
__global__ __launch_bounds__(128) void pb_k(
    const float* __restrict__ pair, const float* __restrict__ gam,
    const float* __restrict__ bet, const float* __restrict__ Wp,
    float* __restrict__ PB)
{
    const int w    = threadIdx.x >> 5;
    const int lane = threadIdx.x & 31;
    const int pid  = blockIdx.x * 4 + w;
    float4 x4 = *(const float4*)&pair[(size_t)pid * DPAIR + lane * 4];
    float x[4] = {x4.x, x4.y, x4.z, x4.w};
    float s1 = x[0] + x[1] + x[2] + x[3];
    float s2 = x[0]*x[0] + x[1]*x[1] + x[2]*x[2] + x[3]*x[3];
#pragma unroll
    for (int o = 16; o; o >>= 1) {
        s1 += __shfl_xor_sync(0xffffffffu, s1, o);
        s2 += __shfl_xor_sync(0xffffffffu, s2, o);
    }
    float mu  = s1 * (1.f / DPAIR);
    float var = s2 * (1.f / DPAIR) - mu * mu;
    float inv = rsqrtf(var + 1e-5f);

    float acc[8];
#pragma unroll
    for (int hh = 0; hh < 8; hh++) acc[hh] = 0.f;
#pragma unroll
    for (int u = 0; u < 4; u++) {
        int c = lane * 4 + u;
        float nx = (x[u] - mu) * inv * gam[c] + bet[c];
#pragma unroll
        for (int hh = 0; hh < 8; hh++) acc[hh] += nx * Wp[c * 8 + hh];
    }
#pragma unroll
    for (int o = 16; o; o >>= 1)
#pragma unroll
        for (int hh = 0; hh < 8; hh++) acc[hh] += __shfl_xor_sync(0xffffffffu, acc[hh], o);
    if (lane == 0) {
#pragma unroll
        for (int hh = 0; hh < 8; hh++) PB[(size_t)pid * 8 + hh] = acc[hh];
    }
}

// ---------------------------------------------------------------------------
// softmax over dots+pair bias (unchanged)
// ---------------------------------------------------------------------------
__global__ __launch_bounds__(128) void softh_k(
    const float* __restrict__ DOTS, const float* __restrict__ PB,
    float* __restrict__ ATT)
{
    const int i = blockIdx.x;
    const int h = blockIdx.y;
    const int t = threadIdx.x;
    const float* dp = &DOTS[((size_t)h * LL + i) * LL];
    float x[3];
#pragma unroll
    for (int u = 0; u < 3; u++) {
        int j = t + u * 128;
        x[u] = dp[j] + PB[((size_t)i * LL + j) * 8 + h];
    }
    __shared__ float red[128];
    float lm = fmaxf(fmaxf(x[0], x[1]), x[2]);
    red[t] = lm; __syncthreads();
    for (int o = 64; o; o >>= 1) { if (t < o) red[t] = fmaxf(red[t], red[t + o]); __syncthreads(); }
    float mx = red[0]; __syncthreads();
    float e[3], ls = 0.f;
#pragma unroll
    for (int u = 0; u < 3; u++) { e[u] = __expf(x[u] - mx); ls += e[u]; }
    red[t] = ls; __syncthreads();
    for (int o = 64; o; o >>= 1) { if (t < o) red[t] += red[t + o]; __syncthreads(); }
    float inv = 1.f / red[0];
    float* ap = &ATT[((size_t)h * LL + i) * LL];
#pragma unroll
    for (int u = 0; u < 3; u++) ap[t + u * 128] = e[u] * inv;
}

// ---------------------------------------------------------------------------
// oh (unchanged)
// ---------------------------------------------------------------------------
__global__ __launch_bounds__(256) void oh_k(
    const float* __restrict__ ATT, const float* __restrict__ VH,
    float* __restrict__ CH)
{
    const int r  = blockIdx.y >> 3;
    const int h  = blockIdx.y & 7;
    const int i0 = blockIdx.x * 32;
    const int t  = threadIdx.x;
    const int ti = t >> 4, tj = t & 15;
    const int li = t >> 3;
    const int j4 = (t & 7) * 4;
    const int d0 = (t & 7) * 8;

    __shared__ float Ats[32][36];
    __shared__ float Vs [32][68];
    float acc[2][4];
#pragma unroll
    for (int a = 0; a < 2; a++)
#pragma unroll
        for (int b = 0; b < 4; b++) acc[a][b] = 0.f;

    const float* arow = &ATT[((size_t)h * LL + (i0 + li)) * LL];

    for (int jt = 0; jt < LL; jt += 32) {
        *(float4*)&Ats[li][j4] = *(const float4*)&arow[jt + j4];
        const float* vp = &VH[((size_t)r * LL + (jt + li)) * INNERD + h * DHEAD + d0];
        *(float4*)&Vs[li][d0]     = *(const float4*)&vp[0];
        *(float4*)&Vs[li][d0 + 4] = *(const float4*)&vp[4];
        __syncthreads();
#pragma unroll
        for (int jj = 0; jj < 32; jj++) {
            float a0 = Ats[ti * 2][jj], a1 = Ats[ti * 2 + 1][jj];
            float4 b4 = *(const float4*)&Vs[jj][tj * 4];
            acc[0][0] += a0 * b4.x; acc[0][1] += a0 * b4.y;
            acc[0][2] += a0 * b4.z; acc[0][3] += a0 * b4.w;
            acc[1][0] += a1 * b4.x; acc[1][1] += a1 * b4.y;
            acc[1][2] += a1 * b4.z; acc[1][3] += a1 * b4.w;
        }
        __syncthreads();
    }
#pragma unroll
    for (int a = 0; a < 2; a++) {
        float* op = &CH[((size_t)r * LL + (i0 + ti * 2 + a)) * INNERD + h * DHEAD + tj * 4];
        float4 o = {acc[a][0], acc[a][1], acc[a][2], acc[a][3]};
        *(float4*)op = o;
    }
}

// ---------------------------------------------------------------------------
// Host launch
// ---------------------------------------------------------------------------
static float* sym(const void* s) {
    void* p = nullptr;
    cudaGetSymbolAddress(&p, s);
    return (float*)p;
}

extern "C" void kernel_launch(void* const* d_in, const int* in_sizes, int n_in,
                              void* d_out, int out_size)
{
    const float* m     = (const float*)d_in[0];
    const float* pair  = (const float*)d_in[1];
    const float* Wq_w  = (const float*)d_in[2];
    const float* Wkv_w = (const float*)d_in[3];
    const float* Wo_w  = (const float*)d_in[4];
    const float* bo_w  = (const float*)d_in[5];
    const float* Wq_h  = (const float*)d_in[6];
    const float* Wkv_h = (const float*)d_in[7];
    const float* Wo_h  = (const float*)d_in[8];
    const float* bo_h  = (const float*)d_in[9];
    const float* ln_g  = (const float*)d_in[10];
    const float* ln_b  = (const float*)d_in[11];
    const float* Wpair = (const float*)d_in[12];
    const float* Wsq   = (const float*)d_in[13];
    const float* bsq   = (const float*)d_in[14];
    const float* Wsk   = (const float*)d_in[15];
    const float* bsk   = (const float*)d_in[16];
    float* out = (float*)d_out;

    float* Q    = sym(g_Q);
    float* K    = sym(g_K);
    float* V    = sym(g_V);
    float* CW   = sym(g_CW);
    float* CH   = sym(g_CH);
    float* KS   = sym(g_KS);
    float* QS   = sym(g_QS);
    float* TIE  = sym(g_TIE);
    float* DOTS = sym(g_DOTS);
    float* PB   = sym(g_PB);
    float* ATT  = sym(g_ATT);
    float* WtQw  = sym(g_WtQw);
    float* WtKVw = sym(g_WtKVw);
    float* WtOw  = sym(g_WtOw);
    float* WtQh  = sym(g_WtQh);
    float* WtKVh = sym(g_WtKVh);
    float* WtOh  = sym(g_WtOh);
    float* WtSq  = sym(g_WtSq);
    float* WtSk  = sym(g_WtSk);

    const dim3 tb(32, 8);
    transpose_k<<<dim3(16, 4), tb>>>(Wq_w,  WtQw,  DDIM,   INNERD);
    transpose_k<<<dim3(32, 4), tb>>>(Wkv_w, WtKVw, DDIM,   2 * INNERD);
    transpose_k<<<dim3(4, 16), tb>>>(Wo_w,  WtOw,  INNERD, DDIM);
    transpose_k<<<dim3(16, 4), tb>>>(Wq_h,  WtQh,  DDIM,   INNERD);
    transpose_k<<<dim3(32, 4), tb>>>(Wkv_h, WtKVh, DDIM,   2 * INNERD);
    transpose_k<<<dim3(4, 16), tb>>>(Wo_h,  WtOh,  INNERD, DDIM);
    transpose_k<<<dim3(4, 4),  tb>>>(Wsq,   WtSq,  DDIM,   DDIM);
    transpose_k<<<dim3(4, 4),  tb>>>(Wsk,   WtSk,  DDIM,   DDIM);

    const dim3 gBig(4, 384);    // N=512, M=49152
    const dim3 gD  (1, 384);    // N=128, M=49152

    // ---- width (column) attention ----
    gemm_tc<<<gBig, 256>>>(m, DDIM, WtQw,               nullptr, Q, INNERD, DDIM, 1.f, 0.f);
    gemm_tc<<<gBig, 256>>>(m, DDIM, WtKVw,              nullptr, K, INNERD, DDIM, 1.f, 0.f);
    gemm_tc<<<gBig, 256>>>(m, DDIM, WtKVw + 512 * DDIM, nullptr, V, INNERD, DDIM, 1.f, 0.f);
    col_attn_k<<<LL * HHEADS, 128>>>(Q, K, V, CW);

    // ---- height (row) attention ----
    gemm_tc<<<gBig, 256>>>(m, DDIM, WtQh,               nullptr, Q, INNERD, DDIM, 1.f, 0.f);
    gemm_tc<<<gBig, 256>>>(m, DDIM, WtKVh,              nullptr, K, INNERD, DDIM, 1.f, 0.f);
    gemm_tc<<<gBig, 256>>>(m, DDIM, WtKVh + 512 * DDIM, nullptr, V, INNERD, DDIM, 1.f, 0.f);

    gemm_tc<<<dim3(1, 3), 256>>>(m, DDIM, WtSq, bsq, QS, DDIM, DDIM, 1.f, 0.f);
    gemm_tc<<<gD, 256>>>(m, DDIM, WtSk, bsk, KS, DDIM, DDIM, 1.f, 0.f);

    tie_k<<<LL * HHEADS, 128>>>(QS, KS, TIE);
    dots_k<<<dim3(12, 12, HHEADS), 256>>>(TIE, Q, K, DOTS);
    pb_k<<<LL * LL / 4, 128>>>(pair, ln_g, ln_b, Wpair, PB);
    softh_k<<<dim3(LL, HHEADS), 128>>>(DOTS, PB, ATT);
    oh_k<<<dim3(12, RR * HHEADS), 256>>>(ATT, V, CH);

    // ---- fused output: out = 0.5*(CW@Wo_w + bo_w) + 0.5*(CH@Wo_h + bo_h) ----
    gemm_tc<<<gD, 256>>>(CW, INNERD, WtOw, bo_w, out, DDIM, INNERD, 0.5f, 0.f);
    gemm_tc<<<gD, 256>>>(CH, INNERD, WtOh, bo_h, out, DDIM, INNERD, 0.5f, 1.f);
}

// round 4
// speedup vs baseline: 1.1349x; 1.0019x over previous
#include <cuda_runtime.h>
#include <cstdint>

// Problem constants
#define RR     128
#define LL     384
#define DDIM   128
#define HHEADS 8
#define DHEAD  64
#define DPAIR  128
#define INNERD 512
#define ML     (RR*LL)
#define DHW    16

// ---------------- scratch (device globals; no allocation allowed) ----------
__device__ float g_Q [ML*INNERD];
__device__ float g_K [ML*INNERD];
__device__ float g_V [ML*INNERD];
__device__ float g_CW[ML*INNERD];
__device__ float g_CH[ML*INNERD];
__device__ float g_KS[ML*DDIM];
__device__ float g_QS[LL*DDIM];
__device__ float g_TIE [LL*HHEADS*RR];
__device__ float g_DOTS[HHEADS*LL*LL];
__device__ float g_PB  [LL*LL*HHEADS];
__device__ float g_ATT [HHEADS*LL*LL];
// transposed weights (K-major, [N][K])
__device__ float g_WtQw [INNERD*DDIM];
__device__ float g_WtKVw[2*INNERD*DDIM];
__device__ float g_WtOw [DDIM*INNERD];
__device__ float g_WtQh [INNERD*DDIM];
__device__ float g_WtKVh[2*INNERD*DDIM];
__device__ float g_WtOh [DDIM*INNERD];
__device__ float g_WtSq [DDIM*DDIM];
__device__ float g_WtSk [DDIM*DDIM];

// ---------------------------------------------------------------------------
// tf32 warp MMA: D(16x8) += A(16x8,row) * B(8x8,col)
// ---------------------------------------------------------------------------
__device__ __forceinline__ void mma_tf32(float* d, const uint32_t* a, const uint32_t* b) {
    asm volatile(
        "mma.sync.aligned.m16n8k8.row.col.f32.tf32.tf32.f32 "
        "{%0,%1,%2,%3}, {%4,%5,%6,%7}, {%8,%9}, {%0,%1,%2,%3};"
        : "+f"(d[0]), "+f"(d[1]), "+f"(d[2]), "+f"(d[3])
        : "r"(a[0]), "r"(a[1]), "r"(a[2]), "r"(a[3]), "r"(b[0]), "r"(b[1]));
}
__device__ __forceinline__ uint32_t f2tf32(float v) {
    uint32_t o;
    asm("cvt.rna.tf32.f32 %0, %1;" : "=r"(o) : "f"(v));
    return o;
}

// ---------------------------------------------------------------------------
// Weight transpose: Wt[n*K + k] = W[k*N + n].  grid (N/32, K/32), block (32,8)
// ---------------------------------------------------------------------------
__global__ void transpose_k(const float* __restrict__ W, float* __restrict__ Wt,
                            int K, int N)
{
    __shared__ float tile[32][33];
    int kb = blockIdx.y * 32, nb = blockIdx.x * 32;
    int tx = threadIdx.x, ty = threadIdx.y;
#pragma unroll
    for (int i = 0; i < 32; i += 8)
        tile[ty + i][tx] = W[(size_t)(kb + ty + i) * N + nb + tx];
    __syncthreads();
#pragma unroll
    for (int i = 0; i < 32; i += 8)
        Wt[(size_t)(nb + ty + i) * K + kb + tx] = tile[tx][ty + i];
}

// ---------------------------------------------------------------------------
// tf32 tensor-core GEMM:
//   C[m][n] = alpha*(sum_k X[m][k]*Wt[n][k] + bias[n]) + beta*C
// Block 128x128, BK=16, 256 threads = 8 warps (4 rows x 2 cols), warp 32x64.
// ---------------------------------------------------------------------------
__global__ __launch_bounds__(256) void gemm_tc(
    const float* __restrict__ X, int ldx,
    const float* __restrict__ Wt,          // [N][K] K-major
    const float* __restrict__ bias,
    float* __restrict__ C, int ldc,
    int K, float alpha, float beta)
{
    __shared__ float As[128 * 20];   // [m][k], stride 20 (conflict-free frags)
    __shared__ float Bs[128 * 20];   // [n][k]

    const int t    = threadIdx.x;
    const int lane = t & 31;
    const int wid  = t >> 5;
    const int wm   = (wid & 3) * 32;     // warp row offset in tile
    const int wn   = (wid >> 2) * 64;    // warp col offset in tile
    const int row0 = blockIdx.y * 128;
    const int col0 = blockIdx.x * 128;

    float acc[2][8][4];
#pragma unroll
    for (int mt = 0; mt < 2; mt++)
#pragma unroll
        for (int nt = 0; nt < 8; nt++)
#pragma unroll
            for (int i = 0; i < 4; i++) acc[mt][nt][i] = 0.f;

    const int lr = t >> 2;          // 0..63 load row
    const int lc = (t & 3) * 4;     // 0,4,8,12 load k

    for (int k0 = 0; k0 < K; k0 += 16) {
#pragma unroll
        for (int half = 0; half < 2; half++) {
            int r = lr + half * 64;
            float4 va = *(const float4*)&X [(size_t)(row0 + r) * ldx + k0 + lc];
            float4 vb = *(const float4*)&Wt[(size_t)(col0 + r) * K   + k0 + lc];
            uint4 ua, ub;
            ua.x = f2tf32(va.x); ua.y = f2tf32(va.y);
            ua.z = f2tf32(va.z); ua.w = f2tf32(va.w);
            ub.x = f2tf32(vb.x); ub.y = f2tf32(vb.y);
            ub.z = f2tf32(vb.z); ub.w = f2tf32(vb.w);
            *(uint4*)&As[r * 20 + lc] = ua;
            *(uint4*)&Bs[r * 20 + lc] = ub;
        }
        __syncthreads();
#pragma unroll
        for (int ks = 0; ks < 16; ks += 8) {
            uint32_t af[2][4];
            const int fr = lane >> 2;      // 0..7
            const int fc = ks + (lane & 3);
#pragma unroll
            for (int mt = 0; mt < 2; mt++) {
                int r = wm + mt * 16 + fr;
                af[mt][0] = __float_as_uint(As[r * 20 + fc]);
                af[mt][1] = __float_as_uint(As[(r + 8) * 20 + fc]);
                af[mt][2] = __float_as_uint(As[r * 20 + fc + 4]);
                af[mt][3] = __float_as_uint(As[(r + 8) * 20 + fc + 4]);
            }
#pragma unroll
            for (int nt = 0; nt < 8; nt++) {
                uint32_t bf[2];
                int n = wn + nt * 8 + fr;
                bf[0] = __float_as_uint(Bs[n * 20 + fc]);
                bf[1] = __float_as_uint(Bs[n * 20 + fc + 4]);
                mma_tf32(acc[0][nt], af[0], bf);
                mma_tf32(acc[1][nt], af[1], bf);
            }
        }
        __syncthreads();
    }

    // ---- epilogue ----
#pragma unroll
    for (int mt = 0; mt < 2; mt++) {
#pragma unroll
        for (int nt = 0; nt < 8; nt++) {
            int rg = row0 + wm + mt * 16 + (lane >> 2);
            int cg = col0 + wn + nt * 8 + (lane & 3) * 2;
            float bx = 0.f, by = 0.f;
            if (bias) { bx = bias[cg]; by = bias[cg + 1]; }
#pragma unroll
            for (int half = 0; half < 2; half++) {
                int r = rg + half * 8;
                float vx = alpha * (acc[mt][nt][half * 2 + 0] + bx);
                float vy = alpha * (acc[mt][nt][half * 2 + 1] + by);
                float2* cp = (float2*)&C[(size_t)r * ldc + cg];
                if (beta != 0.f) {
                    float2 o = *cp;
                    vx += beta * o.x; vy += beta * o.y;
                }
                float2 v = {vx, vy};
                *cp = v;
            }
        }
    }
}

// ---------------------------------------------------------------------------
// Column ("width") attention (unchanged)
// ---------------------------------------------------------------------------
__global__ __launch_bounds__(128) void col_attn_k(
    const float* __restrict__ Q, const float* __restrict__ K,
    const float* __restrict__ V, float* __restrict__ CW)
{
    const int l = blockIdx.x >> 3;
    const int h = blockIdx.x & 7;
    const int i = threadIdx.x;

    __shared__ float Ks[64][64];
    __shared__ float Vs[64][64];

    float q[64];
    {
        const float* qp = &Q[((size_t)i * LL + l) * INNERD + h * DHEAD];
#pragma unroll
        for (int d = 0; d < 64; d += 4) {
            float4 v4 = *(const float4*)&qp[d];
            q[d] = v4.x; q[d + 1] = v4.y; q[d + 2] = v4.z; q[d + 3] = v4.w;
        }
    }

    float mx = -1e30f, lsum = 0.f, acc[64];
#pragma unroll
    for (int d = 0; d < 64; d++) acc[d] = 0.f;

    const int jr = i >> 1;
    const int dh = (i & 1) * 32;

    for (int c = 0; c < 2; c++) {
        __syncthreads();
        const float* kp = &K[((size_t)(c * 64 + jr) * LL + l) * INNERD + h * DHEAD + dh];
        const float* vp = &V[((size_t)(c * 64 + jr) * LL + l) * INNERD + h * DHEAD + dh];
#pragma unroll
        for (int u = 0; u < 32; u += 4) {
            *(float4*)&Ks[jr][dh + u] = *(const float4*)&kp[u];
            *(float4*)&Vs[jr][dh + u] = *(const float4*)&vp[u];
        }
        __syncthreads();

        for (int j = 0; j < 64; j++) {
            float s = 0.f;
#pragma unroll
            for (int d = 0; d < 64; d++) s += q[d] * Ks[j][d];
            s *= 0.125f;
            float nm   = fmaxf(mx, s);
            float corr = __expf(mx - nm);
            float p    = __expf(s - nm);
            lsum = lsum * corr + p;
#pragma unroll
            for (int d = 0; d < 64; d++) acc[d] = acc[d] * corr + p * Vs[j][d];
            mx = nm;
        }
    }

    float inv = 1.f / lsum;
    float* op = &CW[((size_t)i * LL + l) * INNERD + h * DHEAD];
#pragma unroll
    for (int d = 0; d < 64; d += 4) {
        float4 o = {acc[d] * inv, acc[d + 1] * inv, acc[d + 2] * inv, acc[d + 3] * inv};
        *(float4*)&op[d] = o;
    }
}

// ---------------------------------------------------------------------------
// Row-tie weights (unchanged)
// ---------------------------------------------------------------------------
__global__ __launch_bounds__(128) void tie_k(
    const float* __restrict__ QS, const float* __restrict__ KS,
    float* __restrict__ TIE)
{
    const int l = blockIdx.x >> 3;
    const int h = blockIdx.x & 7;
    const int r = threadIdx.x;
    const float* q = &QS[l * DDIM + h * DHW];
    const float* k = &KS[((size_t)r * LL + l) * DDIM + h * DHW];
    float s = 0.f;
#pragma unroll
    for (int d = 0; d < DHW; d++) s += q[d] * k[d];
    s *= 0.25f;

    __shared__ float red[128];
    red[r] = s; __syncthreads();
    for (int o = 64; o; o >>= 1) { if (r < o) red[r] = fmaxf(red[r], red[r + o]); __syncthreads(); }
    float m = red[0]; __syncthreads();
    float e = __expf(s - m);
    red[r] = e; __syncthreads();
    for (int o = 64; o; o >>= 1) { if (r < o) red[r] += red[r + o]; __syncthreads(); }
    TIE[(l * HHEADS + h) * RR + r] = e / red[0];
}

// ---------------------------------------------------------------------------
// dots_h (unchanged this round)
// ---------------------------------------------------------------------------
__global__ __launch_bounds__(256) void dots_k(
    const float* __restrict__ TIE, const float* __restrict__ QH,
    const float* __restrict__ KH, float* __restrict__ DOTS)
{
    const int h  = blockIdx.z;
    const int i0 = blockIdx.y * 32;
    const int j0 = blockIdx.x * 32;
    const int t  = threadIdx.x;
    const int ti = t >> 4, tj = t & 15;
    const int li = t >> 3;
    const int d0 = (t & 7) * 8;

    __shared__ float As[64][33];
    __shared__ float Bs[64][33];
    float acc00 = 0, acc01 = 0, acc10 = 0, acc11 = 0;

    for (int r = 0; r < RR; r++) {
        float wv = TIE[((i0 + li) * HHEADS + h) * RR + r];
        const float* qp = &QH[((size_t)r * LL + (i0 + li)) * INNERD + h * DHEAD + d0];
        const float* kp = &KH[((size_t)r * LL + (j0 + li)) * INNERD + h * DHEAD + d0];
#pragma unroll
        for (int u = 0; u < 8; u++) {
            As[d0 + u][li] = wv * qp[u];
            Bs[d0 + u][li] = kp[u];
        }
        __syncthreads();
#pragma unroll
        for (int d = 0; d < 64; d++) {
            float a0 = As[d][ti * 2], a1 = As[d][ti * 2 + 1];
            float b0 = Bs[d][tj * 2], b1 = Bs[d][tj * 2 + 1];
            acc00 += a0 * b0; acc01 += a0 * b1;
            acc10 += a1 * b0; acc11 += a1 * b1;
        }
        __syncthreads();
    }
    float* dp = &DOTS[(size_t)h * LL * LL];
    dp[(i0 + ti * 2 + 0) * LL + (j0 + tj * 2 + 0)] = acc00 * 0.125f;
    dp[(i0 + ti * 2 + 0) * LL + (j0 + tj * 2 + 1)] = acc01 * 0.125f;
    dp[(i0 + ti * 2 + 1) * LL + (j0 + tj * 2 + 0)] = acc10 * 0.125f;
    dp[(i0 + ti * 2 + 1) * LL + (j0 + tj * 2 + 1)] = acc11 * 0.125f;
}

// ---------------------------------------------------------------------------
// Pair bias (unchanged)
// ---------------------------------------------------------------------------
__global__ __launch_bounds__(128) void pb_k(
    const float* __restrict__ pair, const float* __restrict__ gam,
    const float* __restrict__ bet, const float* __restrict__ Wp,
    float* __restrict__ PB)
{
    const int w    = threadIdx.x >> 5;
    const int lane = threadIdx.x & 31;
    const int pid  = blockIdx.x * 4 + w;
    float4 x4 = *(const float4*)&pair[(size_t)pid * DPAIR + lane * 4];
    float x[4] = {x4.x, x4.y, x4.z, x4.w};
    float s1 = x[0] + x[1] + x[2] + x[3];
    float s2 = x[0]*x[0] + x[1]*x[1] + x[2]*x[2] + x[3]*x[3];
#pragma unroll
    for (int o = 16; o; o >>= 1) {
        s1 += __shfl_xor_sync(0xffffffffu, s1, o);
        s2 += __shfl_xor_sync(0xffffffffu, s2, o);
    }
    float mu  = s1 * (1.f / DPAIR);
    float var = s2 * (1.f / DPAIR) - mu * mu;
    float inv = rsqrtf(var + 1e-5f);

    float acc[8];
#pragma unroll
    for (int hh = 0; hh < 8; hh++) acc[hh] = 0.f;
#pragma unroll
    for (int u = 0; u < 4; u++) {
        int c = lane * 4 + u;
        float nx = (x[u] - mu) * inv * gam[c] + bet[c];
#pragma unroll
        for (int hh = 0; hh < 8; hh++) acc[hh] += nx * Wp[c * 8 + hh];
    }
#pragma unroll
    for (int o = 16; o; o >>= 1)
#pragma unroll
        for (int hh = 0; hh < 8; hh++) acc[hh] += __shfl_xor_sync(0xffffffffu, acc[hh], o);
    if (lane == 0) {
#pragma unroll
        for (int hh = 0; hh < 8; hh++) PB[(size_t)pid * 8 + hh] = acc[hh];
    }
}

// ---------------------------------------------------------------------------
// softmax over dots+pair bias (unchanged)
// ---------------------------------------------------------------------------
__global__ __launch_bounds__(128) void softh_k(
    const float* __restrict__ DOTS, const float* __restrict__ PB,
    float* __restrict__ ATT)
{
    const int i = blockIdx.x;
    const int h = blockIdx.y;
    const int t = threadIdx.x;
    const float* dp = &DOTS[((size_t)h * LL + i) * LL];
    float x[3];
#pragma unroll
    for (int u = 0; u < 3; u++) {
        int j = t + u * 128;
        x[u] = dp[j] + PB[((size_t)i * LL + j) * 8 + h];
    }
    __shared__ float red[128];
    float lm = fmaxf(fmaxf(x[0], x[1]), x[2]);
    red[t] = lm; __syncthreads();
    for (int o = 64; o; o >>= 1) { if (t < o) red[t] = fmaxf(red[t], red[t + o]); __syncthreads(); }
    float mx = red[0]; __syncthreads();
    float e[3], ls = 0.f;
#pragma unroll
    for (int u = 0; u < 3; u++) { e[u] = __expf(x[u] - mx); ls += e[u]; }
    red[t] = ls; __syncthreads();
    for (int o = 64; o; o >>= 1) { if (t < o) red[t] += red[t + o]; __syncthreads(); }
    float inv = 1.f / red[0];
    float* ap = &ATT[((size_t)h * LL + i) * LL];
#pragma unroll
    for (int u = 0; u < 3; u++) ap[t + u * 128] = e[u] * inv;
}

// ---------------------------------------------------------------------------
// oh (unchanged)
// ---------------------------------------------------------------------------
__global__ __launch_bounds__(256) void oh_k(
    const float* __restrict__ ATT, const float* __restrict__ VH,
    float* __restrict__ CH)
{
    const int r  = blockIdx.y >> 3;
    const int h  = blockIdx.y & 7;
    const int i0 = blockIdx.x * 32;
    const int t  = threadIdx.x;
    const int ti = t >> 4, tj = t & 15;
    const int li = t >> 3;
    const int j4 = (t & 7) * 4;
    const int d0 = (t & 7) * 8;

    __shared__ float Ats[32][36];
    __shared__ float Vs [32][68];
    float acc[2][4];
#pragma unroll
    for (int a = 0; a < 2; a++)
#pragma unroll
        for (int b = 0; b < 4; b++) acc[a][b] = 0.f;

    const float* arow = &ATT[((size_t)h * LL + (i0 + li)) * LL];

    for (int jt = 0; jt < LL; jt += 32) {
        *(float4*)&Ats[li][j4] = *(const float4*)&arow[jt + j4];
        const float* vp = &VH[((size_t)r * LL + (jt + li)) * INNERD + h * DHEAD + d0];
        *(float4*)&Vs[li][d0]     = *(const float4*)&vp[0];
        *(float4*)&Vs[li][d0 + 4] = *(const float4*)&vp[4];
        __syncthreads();
#pragma unroll
        for (int jj = 0; jj < 32; jj++) {
            float a0 = Ats[ti * 2][jj], a1 = Ats[ti * 2 + 1][jj];
            float4 b4 = *(const float4*)&Vs[jj][tj * 4];
            acc[0][0] += a0 * b4.x; acc[0][1] += a0 * b4.y;
            acc[0][2] += a0 * b4.z; acc[0][3] += a0 * b4.w;
            acc[1][0] += a1 * b4.x; acc[1][1] += a1 * b4.y;
            acc[1][2] += a1 * b4.z; acc[1][3] += a1 * b4.w;
        }
        __syncthreads();
    }
#pragma unroll
    for (int a = 0; a < 2; a++) {
        float* op = &CH[((size_t)r * LL + (i0 + ti * 2 + a)) * INNERD + h * DHEAD + tj * 4];
        float4 o = {acc[a][0], acc[a][1], acc[a][2], acc[a][3]};
        *(float4*)op = o;
    }
}

// ---------------------------------------------------------------------------
// Host launch
// ---------------------------------------------------------------------------
static float* sym(const void* s) {
    void* p = nullptr;
    cudaGetSymbolAddress(&p, s);
    return (float*)p;
}

extern "C" void kernel_launch(void* const* d_in, const int* in_sizes, int n_in,
                              void* d_out, int out_size)
{
    const float* m     = (const float*)d_in[0];
    const float* pair  = (const float*)d_in[1];
    const float* Wq_w  = (const float*)d_in[2];
    const float* Wkv_w = (const float*)d_in[3];
    const float* Wo_w  = (const float*)d_in[4];
    const float* bo_w  = (const float*)d_in[5];
    const float* Wq_h  = (const float*)d_in[6];
    const float* Wkv_h = (const float*)d_in[7];
    const float* Wo_h  = (const float*)d_in[8];
    const float* bo_h  = (const float*)d_in[9];
    const float* ln_g  = (const float*)d_in[10];
    const float* ln_b  = (const float*)d_in[11];
    const float* Wpair = (const float*)d_in[12];
    const float* Wsq   = (const float*)d_in[13];
    const float* bsq   = (const float*)d_in[14];
    const float* Wsk   = (const float*)d_in[15];
    const float* bsk   = (const float*)d_in[16];
    float* out = (float*)d_out;

    float* Q    = sym(g_Q);
    float* K    = sym(g_K);
    float* V    = sym(g_V);
    float* CW   = sym(g_CW);
    float* CH   = sym(g_CH);
    float* KS   = sym(g_KS);
    float* QS   = sym(g_QS);
    float* TIE  = sym(g_TIE);
    float* DOTS = sym(g_DOTS);
    float* PB   = sym(g_PB);
    float* ATT  = sym(g_ATT);
    float* WtQw  = sym(g_WtQw);
    float* WtKVw = sym(g_WtKVw);
    float* WtOw  = sym(g_WtOw);
    float* WtQh  = sym(g_WtQh);
    float* WtKVh = sym(g_WtKVh);
    float* WtOh  = sym(g_WtOh);
    float* WtSq  = sym(g_WtSq);
    float* WtSk  = sym(g_WtSk);

    const dim3 tb(32, 8);
    transpose_k<<<dim3(16, 4), tb>>>(Wq_w,  WtQw,  DDIM,   INNERD);
    transpose_k<<<dim3(32, 4), tb>>>(Wkv_w, WtKVw, DDIM,   2 * INNERD);
    transpose_k<<<dim3(4, 16), tb>>>(Wo_w,  WtOw,  INNERD, DDIM);
    transpose_k<<<dim3(16, 4), tb>>>(Wq_h,  WtQh,  DDIM,   INNERD);
    transpose_k<<<dim3(32, 4), tb>>>(Wkv_h, WtKVh, DDIM,   2 * INNERD);
    transpose_k<<<dim3(4, 16), tb>>>(Wo_h,  WtOh,  INNERD, DDIM);
    transpose_k<<<dim3(4, 4),  tb>>>(Wsq,   WtSq,  DDIM,   DDIM);
    transpose_k<<<dim3(4, 4),  tb>>>(Wsk,   WtSk,  DDIM,   DDIM);

    const dim3 gBig(4, 384);    // N=512, M=49152
    const dim3 gD  (1, 384);    // N=128, M=49152

    // ---- width (column) attention ----
    gemm_tc<<<gBig, 256>>>(m, DDIM, WtQw,               nullptr, Q, INNERD, DDIM, 1.f, 0.f);
    gemm_tc<<<gBig, 256>>>(m, DDIM, WtKVw,              nullptr, K, INNERD, DDIM, 1.f, 0.f);
    gemm_tc<<<gBig, 256>>>(m, DDIM, WtKVw + 512 * DDIM, nullptr, V, INNERD, DDIM, 1.f, 0.f);
    col_attn_k<<<LL * HHEADS, 128>>>(Q, K, V, CW);

    // ---- height (row) attention ----
    gemm_tc<<<gBig, 256>>>(m, DDIM, WtQh,               nullptr, Q, INNERD, DDIM, 1.f, 0.f);
    gemm_tc<<<gBig, 256>>>(m, DDIM, WtKVh,              nullptr, K, INNERD, DDIM, 1.f, 0.f);
    gemm_tc<<<gBig, 256>>>(m, DDIM, WtKVh + 512 * DDIM, nullptr, V, INNERD, DDIM, 1.f, 0.f);

    gemm_tc<<<dim3(1, 3), 256>>>(m, DDIM, WtSq, bsq, QS, DDIM, DDIM, 1.f, 0.f);
    gemm_tc<<<gD, 256>>>(m, DDIM, WtSk, bsk, KS, DDIM, DDIM, 1.f, 0.f);

    tie_k<<<LL * HHEADS, 128>>>(QS, KS, TIE);
    dots_k<<<dim3(12, 12, HHEADS), 256>>>(TIE, Q, K, DOTS);
    pb_k<<<LL * LL / 4, 128>>>(pair, ln_g, ln_b, Wpair, PB);
    softh_k<<<dim3(LL, HHEADS), 128>>>(DOTS, PB, ATT);
    oh_k<<<dim3(12, RR * HHEADS), 256>>>(ATT, V, CH);

    // ---- fused output: out = 0.5*(CW@Wo_w + bo_w) + 0.5*(CH@Wo_h + bo_h) ----
    gemm_tc<<<gD, 256>>>(CW, INNERD, WtOw, bo_w, out, DDIM, INNERD, 0.5f, 0.f);
    gemm_tc<<<gD, 256>>>(CH, INNERD, WtOh, bo_h, out, DDIM, INNERD, 0.5f, 1.f);
}

// round 5
// speedup vs baseline: 1.9456x; 1.7144x over previous
#include <cuda_runtime.h>
#include <cstdint>

#define RR     128
#define LL     384
#define DDIM   128
#define HHEADS 8
#define DHEAD  64
#define DPAIR  128
#define INNERD 512
#define ML     (RR*LL)
#define DHW    16

// ---------------- scratch ----------
__device__ float g_Q [ML*INNERD];
__device__ float g_K [ML*INNERD];
__device__ float g_V [ML*INNERD];
__device__ float g_CW[ML*INNERD];
__device__ float g_CH[ML*INNERD];
__device__ float g_KS[ML*DDIM];
__device__ float g_QS[LL*DDIM];
__device__ float g_TIE  [HHEADS*RR*LL];     // [h][r][l]
__device__ float g_DOTS [HHEADS*LL*LL];
__device__ float g_DOTS2[HHEADS*LL*LL];
__device__ float g_PB  [LL*LL*HHEADS];
__device__ float g_ATT [HHEADS*LL*LL];
__device__ float g_WtQw [INNERD*DDIM];
__device__ float g_WtKVw[2*INNERD*DDIM];
__device__ float g_WtOw [DDIM*INNERD];
__device__ float g_WtQh [INNERD*DDIM];
__device__ float g_WtKVh[2*INNERD*DDIM];
__device__ float g_WtOh [DDIM*INNERD];
__device__ float g_WtSq [DDIM*DDIM];
__device__ float g_WtSk [DDIM*DDIM];

// ---------------------------------------------------------------------------
__device__ __forceinline__ void mma_tf32(float* d, const uint32_t* a, const uint32_t* b) {
    asm volatile(
        "mma.sync.aligned.m16n8k8.row.col.f32.tf32.tf32.f32 "
        "{%0,%1,%2,%3}, {%4,%5,%6,%7}, {%8,%9}, {%0,%1,%2,%3};"
        : "+f"(d[0]), "+f"(d[1]), "+f"(d[2]), "+f"(d[3])
        : "r"(a[0]), "r"(a[1]), "r"(a[2]), "r"(a[3]), "r"(b[0]), "r"(b[1]));
}
__device__ __forceinline__ uint32_t f2tf32(float v) {
    uint32_t o;
    asm("cvt.rna.tf32.f32 %0, %1;" : "=r"(o) : "f"(v));
    return o;
}

// ---------------------------------------------------------------------------
__global__ void transpose_k(const float* __restrict__ W, float* __restrict__ Wt,
                            int K, int N)
{
    __shared__ float tile[32][33];
    int kb = blockIdx.y * 32, nb = blockIdx.x * 32;
    int tx = threadIdx.x, ty = threadIdx.y;
#pragma unroll
    for (int i = 0; i < 32; i += 8)
        tile[ty + i][tx] = W[(size_t)(kb + ty + i) * N + nb + tx];
    __syncthreads();
#pragma unroll
    for (int i = 0; i < 32; i += 8)
        Wt[(size_t)(nb + ty + i) * K + kb + tx] = tile[tx][ty + i];
}

// ---------------------------------------------------------------------------
// tf32 tensor-core GEMM (block 128x128, BK=16, 8 warps)
// ---------------------------------------------------------------------------
__global__ __launch_bounds__(256) void gemm_tc(
    const float* __restrict__ X, int ldx,
    const float* __restrict__ Wt,
    const float* __restrict__ bias,
    float* __restrict__ C, int ldc,
    int K, float alpha, float beta)
{
    __shared__ float As[128 * 20];
    __shared__ float Bs[128 * 20];

    const int t    = threadIdx.x;
    const int lane = t & 31;
    const int wid  = t >> 5;
    const int wm   = (wid & 3) * 32;
    const int wn   = (wid >> 2) * 64;
    const int row0 = blockIdx.y * 128;
    const int col0 = blockIdx.x * 128;

    float acc[2][8][4];
#pragma unroll
    for (int mt = 0; mt < 2; mt++)
#pragma unroll
        for (int nt = 0; nt < 8; nt++)
#pragma unroll
            for (int i = 0; i < 4; i++) acc[mt][nt][i] = 0.f;

    const int lr = t >> 2;
    const int lc = (t & 3) * 4;

    for (int k0 = 0; k0 < K; k0 += 16) {
#pragma unroll
        for (int half = 0; half < 2; half++) {
            int r = lr + half * 64;
            float4 va = *(const float4*)&X [(size_t)(row0 + r) * ldx + k0 + lc];
            float4 vb = *(const float4*)&Wt[(size_t)(col0 + r) * K   + k0 + lc];
            uint4 ua, ub;
            ua.x = f2tf32(va.x); ua.y = f2tf32(va.y);
            ua.z = f2tf32(va.z); ua.w = f2tf32(va.w);
            ub.x = f2tf32(vb.x); ub.y = f2tf32(vb.y);
            ub.z = f2tf32(vb.z); ub.w = f2tf32(vb.w);
            *(uint4*)&As[r * 20 + lc] = ua;
            *(uint4*)&Bs[r * 20 + lc] = ub;
        }
        __syncthreads();
#pragma unroll
        for (int ks = 0; ks < 16; ks += 8) {
            uint32_t af[2][4];
            const int fr = lane >> 2;
            const int fc = ks + (lane & 3);
#pragma unroll
            for (int mt = 0; mt < 2; mt++) {
                int r = wm + mt * 16 + fr;
                af[mt][0] = __float_as_uint(As[r * 20 + fc]);
                af[mt][1] = __float_as_uint(As[(r + 8) * 20 + fc]);
                af[mt][2] = __float_as_uint(As[r * 20 + fc + 4]);
                af[mt][3] = __float_as_uint(As[(r + 8) * 20 + fc + 4]);
            }
#pragma unroll
            for (int nt = 0; nt < 8; nt++) {
                uint32_t bf[2];
                int n = wn + nt * 8 + fr;
                bf[0] = __float_as_uint(Bs[n * 20 + fc]);
                bf[1] = __float_as_uint(Bs[n * 20 + fc + 4]);
                mma_tf32(acc[0][nt], af[0], bf);
                mma_tf32(acc[1][nt], af[1], bf);
            }
        }
        __syncthreads();
    }

#pragma unroll
    for (int mt = 0; mt < 2; mt++) {
#pragma unroll
        for (int nt = 0; nt < 8; nt++) {
            int rg = row0 + wm + mt * 16 + (lane >> 2);
            int cg = col0 + wn + nt * 8 + (lane & 3) * 2;
            float bx = 0.f, by = 0.f;
            if (bias) { bx = bias[cg]; by = bias[cg + 1]; }
#pragma unroll
            for (int half = 0; half < 2; half++) {
                int r = rg + half * 8;
                float vx = alpha * (acc[mt][nt][half * 2 + 0] + bx);
                float vy = alpha * (acc[mt][nt][half * 2 + 1] + by);
                float2* cp = (float2*)&C[(size_t)r * ldc + cg];
                if (beta != 0.f) {
                    float2 o = *cp;
                    vx += beta * o.x; vy += beta * o.y;
                }
                float2 v = {vx, vy};
                *cp = v;
            }
        }
    }
}

// ---------------------------------------------------------------------------
// dots_tc: OUT[h,i,j] = 0.125*sum_{r in half} sum_d (wtie[h,r,i]*QH[r,i,h,d]) * KH[r,j,h,d]
// Block 128x128 tile, per-head, K-split x2 (rz). grid (3,3,16), 256 thr.
// ---------------------------------------------------------------------------
__global__ __launch_bounds__(256) void dots_tc(
    const float* __restrict__ TIE,     // [h][r][l]
    const float* __restrict__ QH, const float* __restrict__ KH,
    float* __restrict__ D1, float* __restrict__ D2)
{
    __shared__ float As[128 * 36];
    __shared__ float Bs[128 * 36];
    __shared__ float wv_s[8 * 128];

    const int t    = threadIdx.x;
    const int lane = t & 31;
    const int wid  = t >> 5;
    const int wm   = (wid & 3) * 32;
    const int wn   = (wid >> 2) * 64;
    const int i0 = blockIdx.y * 128;
    const int j0 = blockIdx.x * 128;
    const int h  = blockIdx.z & 7;
    const int rz = blockIdx.z >> 3;

    float acc[2][8][4];
#pragma unroll
    for (int mt = 0; mt < 2; mt++)
#pragma unroll
        for (int nt = 0; nt < 8; nt++)
#pragma unroll
            for (int i = 0; i < 4; i++) acc[mt][nt][i] = 0.f;

    for (int rb = rz * 64; rb < rz * 64 + 64; rb += 8) {
        __syncthreads();
#pragma unroll
        for (int i = 0; i < 4; i++) {
            int e = t + 256 * i;               // 0..1023
            int rr = e >> 7, row = e & 127;
            wv_s[rr * 128 + row] = TIE[((size_t)(h * RR + rb + rr)) * LL + i0 + row];
        }
        __syncthreads();
        for (int rr = 0; rr < 8; rr++) {
            const int r = rb + rr;
            const float* qbase = &QH[((size_t)r * LL + i0) * INNERD + h * DHEAD];
            const float* kbase = &KH[((size_t)r * LL + j0) * INNERD + h * DHEAD];
#pragma unroll
            for (int seg = 0; seg < 2; seg++) {
                const int d0 = seg * 32;
#pragma unroll
                for (int i = 0; i < 4; i++) {
                    int idx = t + 256 * i;       // 0..1023
                    int row = idx >> 3, c4 = (idx & 7) * 4;
                    float wv = wv_s[rr * 128 + row];
                    float4 va = *(const float4*)&qbase[(size_t)row * INNERD + d0 + c4];
                    float4 vb = *(const float4*)&kbase[(size_t)row * INNERD + d0 + c4];
                    uint4 ua, ub;
                    ua.x = f2tf32(va.x * wv); ua.y = f2tf32(va.y * wv);
                    ua.z = f2tf32(va.z * wv); ua.w = f2tf32(va.w * wv);
                    ub.x = f2tf32(vb.x); ub.y = f2tf32(vb.y);
                    ub.z = f2tf32(vb.z); ub.w = f2tf32(vb.w);
                    *(uint4*)&As[row * 36 + c4] = ua;
                    *(uint4*)&Bs[row * 36 + c4] = ub;
                }
                __syncthreads();
#pragma unroll
                for (int ks = 0; ks < 32; ks += 8) {
                    uint32_t af[2][4];
                    const int fr = lane >> 2;
                    const int fc = ks + (lane & 3);
#pragma unroll
                    for (int mt = 0; mt < 2; mt++) {
                        int rw = wm + mt * 16 + fr;
                        af[mt][0] = __float_as_uint(As[rw * 36 + fc]);
                        af[mt][1] = __float_as_uint(As[(rw + 8) * 36 + fc]);
                        af[mt][2] = __float_as_uint(As[rw * 36 + fc + 4]);
                        af[mt][3] = __float_as_uint(As[(rw + 8) * 36 + fc + 4]);
                    }
#pragma unroll
                    for (int nt = 0; nt < 8; nt++) {
                        uint32_t bf[2];
                        int n = wn + nt * 8 + fr;
                        bf[0] = __float_as_uint(Bs[n * 36 + fc]);
                        bf[1] = __float_as_uint(Bs[n * 36 + fc + 4]);
                        mma_tf32(acc[0][nt], af[0], bf);
                        mma_tf32(acc[1][nt], af[1], bf);
                    }
                }
                __syncthreads();
            }
        }
    }

    float* OUT = (rz ? D2 : D1) + (size_t)h * LL * LL;
#pragma unroll
    for (int mt = 0; mt < 2; mt++) {
#pragma unroll
        for (int nt = 0; nt < 8; nt++) {
            int rg = i0 + wm + mt * 16 + (lane >> 2);
            int cg = j0 + wn + nt * 8 + (lane & 3) * 2;
#pragma unroll
            for (int half = 0; half < 2; half++) {
                int rw = rg + half * 8;
                float2 v = {0.125f * acc[mt][nt][half * 2 + 0],
                            0.125f * acc[mt][nt][half * 2 + 1]};
                *(float2*)&OUT[(size_t)rw * LL + cg] = v;
            }
        }
    }
}

// ---------------------------------------------------------------------------
// oh_tc: CH[(r*L+i)*512 + h*64+d] = sum_j ATT[h,i,j]*VH[(r*L+j)*512+h*64+d]
// Block: 128i x 64d tile per (r,h). grid (3, 1024), 256 thr, warp 32x32.
// ---------------------------------------------------------------------------
__global__ __launch_bounds__(256) void oh_tc(
    const float* __restrict__ ATT, const float* __restrict__ VH,
    float* __restrict__ CH)
{
    __shared__ float As[128 * 20];
    __shared__ float Bs[64 * 20];

    const int t    = threadIdx.x;
    const int lane = t & 31;
    const int wid  = t >> 5;
    const int wm   = (wid & 3) * 32;
    const int wn   = (wid >> 2) * 32;
    const int i0 = blockIdx.x * 128;
    const int r  = blockIdx.y >> 3;
    const int h  = blockIdx.y & 7;

    float acc[2][4][4];
#pragma unroll
    for (int mt = 0; mt < 2; mt++)
#pragma unroll
        for (int nt = 0; nt < 4; nt++)
#pragma unroll
            for (int i = 0; i < 4; i++) acc[mt][nt][i] = 0.f;

    for (int k0 = 0; k0 < LL; k0 += 16) {
#pragma unroll
        for (int i = 0; i < 2; i++) {
            int idx = t + 256 * i;               // 0..511
            int row = idx >> 2, c4 = (idx & 3) * 4;
            float4 va = *(const float4*)&ATT[((size_t)h * LL + i0 + row) * LL + k0 + c4];
            uint4 ua;
            ua.x = f2tf32(va.x); ua.y = f2tf32(va.y);
            ua.z = f2tf32(va.z); ua.w = f2tf32(va.w);
            *(uint4*)&As[row * 20 + c4] = ua;
        }
        {
            int kr = t >> 4;                      // 0..15
            int dc = (t & 15) * 4;                // 0..60
            float4 vb = *(const float4*)&VH[((size_t)(r * LL + k0 + kr)) * INNERD + h * DHEAD + dc];
            Bs[(dc + 0) * 20 + kr] = __uint_as_float(f2tf32(vb.x));
            Bs[(dc + 1) * 20 + kr] = __uint_as_float(f2tf32(vb.y));
            Bs[(dc + 2) * 20 + kr] = __uint_as_float(f2tf32(vb.z));
            Bs[(dc + 3) * 20 + kr] = __uint_as_float(f2tf32(vb.w));
        }
        __syncthreads();
#pragma unroll
        for (int ks = 0; ks < 16; ks += 8) {
            uint32_t af[2][4];
            const int fr = lane >> 2;
            const int fc = ks + (lane & 3);
#pragma unroll
            for (int mt = 0; mt < 2; mt++) {
                int rw = wm + mt * 16 + fr;
                af[mt][0] = __float_as_uint(As[rw * 20 + fc]);
                af[mt][1] = __float_as_uint(As[(rw + 8) * 20 + fc]);
                af[mt][2] = __float_as_uint(As[rw * 20 + fc + 4]);
                af[mt][3] = __float_as_uint(As[(rw + 8) * 20 + fc + 4]);
            }
#pragma unroll
            for (int nt = 0; nt < 4; nt++) {
                uint32_t bf[2];
                int n = wn + nt * 8 + fr;
                bf[0] = __float_as_uint(Bs[n * 20 + fc]);
                bf[1] = __float_as_uint(Bs[n * 20 + fc + 4]);
                mma_tf32(acc[0][nt], af[0], bf);
                mma_tf32(acc[1][nt], af[1], bf);
            }
        }
        __syncthreads();
    }

#pragma unroll
    for (int mt = 0; mt < 2; mt++) {
#pragma unroll
        for (int nt = 0; nt < 4; nt++) {
            int rloc = i0 + wm + mt * 16 + (lane >> 2);
            int cg   = wn + nt * 8 + (lane & 3) * 2;
#pragma unroll
            for (int half = 0; half < 2; half++) {
                int rw = rloc + half * 8;
                float2 v = {acc[mt][nt][half * 2 + 0], acc[mt][nt][half * 2 + 1]};
                *(float2*)&CH[((size_t)(r * LL + rw)) * INNERD + h * DHEAD + cg] = v;
            }
        }
    }
}

// ---------------------------------------------------------------------------
// Column attention (fp32, unchanged)
// ---------------------------------------------------------------------------
__global__ __launch_bounds__(128) void col_attn_k(
    const float* __restrict__ Q, const float* __restrict__ K,
    const float* __restrict__ V, float* __restrict__ CW)
{
    const int l = blockIdx.x >> 3;
    const int h = blockIdx.x & 7;
    const int i = threadIdx.x;

    __shared__ float Ks[64][64];
    __shared__ float Vs[64][64];

    float q[64];
    {
        const float* qp = &Q[((size_t)i * LL + l) * INNERD + h * DHEAD];
#pragma unroll
        for (int d = 0; d < 64; d += 4) {
            float4 v4 = *(const float4*)&qp[d];
            q[d] = v4.x; q[d + 1] = v4.y; q[d + 2] = v4.z; q[d + 3] = v4.w;
        }
    }

    float mx = -1e30f, lsum = 0.f, acc[64];
#pragma unroll
    for (int d = 0; d < 64; d++) acc[d] = 0.f;

    const int jr = i >> 1;
    const int dh = (i & 1) * 32;

    for (int c = 0; c < 2; c++) {
        __syncthreads();
        const float* kp = &K[((size_t)(c * 64 + jr) * LL + l) * INNERD + h * DHEAD + dh];
        const float* vp = &V[((size_t)(c * 64 + jr) * LL + l) * INNERD + h * DHEAD + dh];
#pragma unroll
        for (int u = 0; u < 32; u += 4) {
            *(float4*)&Ks[jr][dh + u] = *(const float4*)&kp[u];
            *(float4*)&Vs[jr][dh + u] = *(const float4*)&vp[u];
        }
        __syncthreads();

        for (int j = 0; j < 64; j++) {
            float s = 0.f;
#pragma unroll
            for (int d = 0; d < 64; d++) s += q[d] * Ks[j][d];
            s *= 0.125f;
            float nm   = fmaxf(mx, s);
            float corr = __expf(mx - nm);
            float p    = __expf(s - nm);
            lsum = lsum * corr + p;
#pragma unroll
            for (int d = 0; d < 64; d++) acc[d] = acc[d] * corr + p * Vs[j][d];
            mx = nm;
        }
    }

    float inv = 1.f / lsum;
    float* op = &CW[((size_t)i * LL + l) * INNERD + h * DHEAD];
#pragma unroll
    for (int d = 0; d < 64; d += 4) {
        float4 o = {acc[d] * inv, acc[d + 1] * inv, acc[d + 2] * inv, acc[d + 3] * inv};
        *(float4*)&op[d] = o;
    }
}

// ---------------------------------------------------------------------------
// Row-tie weights -> TIE[h][r][l]
// ---------------------------------------------------------------------------
__global__ __launch_bounds__(128) void tie_k(
    const float* __restrict__ QS, const float* __restrict__ KS,
    float* __restrict__ TIE)
{
    const int l = blockIdx.x >> 3;
    const int h = blockIdx.x & 7;
    const int r = threadIdx.x;
    const float* q = &QS[l * DDIM + h * DHW];
    const float* k = &KS[((size_t)r * LL + l) * DDIM + h * DHW];
    float s = 0.f;
#pragma unroll
    for (int d = 0; d < DHW; d++) s += q[d] * k[d];
    s *= 0.25f;

    __shared__ float red[128];
    red[r] = s; __syncthreads();
    for (int o = 64; o; o >>= 1) { if (r < o) red[r] = fmaxf(red[r], red[r + o]); __syncthreads(); }
    float m = red[0]; __syncthreads();
    float e = __expf(s - m);
    red[r] = e; __syncthreads();
    for (int o = 64; o; o >>= 1) { if (r < o) red[r] += red[r + o]; __syncthreads(); }
    TIE[((size_t)h * RR + r) * LL + l] = e / red[0];
}

// ---------------------------------------------------------------------------
// Pair bias (unchanged)
// ---------------------------------------------------------------------------
__global__ __launch_bounds__(128) void pb_k(
    const float* __restrict__ pair, const float* __restrict__ gam,
    const float* __restrict__ bet, const float* __restrict__ Wp,
    float* __restrict__ PB)
{
    const int w    = threadIdx.x >> 5;
    const int lane = threadIdx.x & 31;
    const int pid  = blockIdx.x * 4 + w;
    float4 x4 = *(const float4*)&pair[(size_t)pid * DPAIR + lane * 4];
    float x[4] = {x4.x, x4.y, x4.z, x4.w};
    float s1 = x[0] + x[1] + x[2] + x[3];
    float s2 = x[0]*x[0] + x[1]*x[1] + x[2]*x[2] + x[3]*x[3];
#pragma unroll
    for (int o = 16; o; o >>= 1) {
        s1 += __shfl_xor_sync(0xffffffffu, s1, o);
        s2 += __shfl_xor_sync(0xffffffffu, s2, o);
    }
    float mu  = s1 * (1.f / DPAIR);
    float var = s2 * (1.f / DPAIR) - mu * mu;
    float inv = rsqrtf(var + 1e-5f);

    float acc[8];
#pragma unroll
    for (int hh = 0; hh < 8; hh++) acc[hh] = 0.f;
#pragma unroll
    for (int u = 0; u < 4; u++) {
        int c = lane * 4 + u;
        float nx = (x[u] - mu) * inv * gam[c] + bet[c];
#pragma unroll
        for (int hh = 0; hh < 8; hh++) acc[hh] += nx * Wp[c * 8 + hh];
    }
#pragma unroll
    for (int o = 16; o; o >>= 1)
#pragma unroll
        for (int hh = 0; hh < 8; hh++) acc[hh] += __shfl_xor_sync(0xffffffffu, acc[hh], o);
    if (lane == 0) {
#pragma unroll
        for (int hh = 0; hh < 8; hh++) PB[(size_t)pid * 8 + hh] = acc[hh];
    }
}

// ---------------------------------------------------------------------------
// softmax over dots1+dots2+pair bias
// ---------------------------------------------------------------------------
__global__ __launch_bounds__(128) void softh_k(
    const float* __restrict__ D1, const float* __restrict__ D2,
    const float* __restrict__ PB, float* __restrict__ ATT)
{
    const int i = blockIdx.x;
    const int h = blockIdx.y;
    const int t = threadIdx.x;
    const float* dp1 = &D1[((size_t)h * LL + i) * LL];
    const float* dp2 = &D2[((size_t)h * LL + i) * LL];
    float x[3];
#pragma unroll
    for (int u = 0; u < 3; u++) {
        int j = t + u * 128;
        x[u] = dp1[j] + dp2[j] + PB[((size_t)i * LL + j) * 8 + h];
    }
    __shared__ float red[128];
    float lm = fmaxf(fmaxf(x[0], x[1]), x[2]);
    red[t] = lm; __syncthreads();
    for (int o = 64; o; o >>= 1) { if (t < o) red[t] = fmaxf(red[t], red[t + o]); __syncthreads(); }
    float mx = red[0]; __syncthreads();
    float e[3], ls = 0.f;
#pragma unroll
    for (int u = 0; u < 3; u++) { e[u] = __expf(x[u] - mx); ls += e[u]; }
    red[t] = ls; __syncthreads();
    for (int o = 64; o; o >>= 1) { if (t < o) red[t] += red[t + o]; __syncthreads(); }
    float inv = 1.f / red[0];
    float* ap = &ATT[((size_t)h * LL + i) * LL];
#pragma unroll
    for (int u = 0; u < 3; u++) ap[t + u * 128] = e[u] * inv;
}

// ---------------------------------------------------------------------------
static float* sym(const void* s) {
    void* p = nullptr;
    cudaGetSymbolAddress(&p, s);
    return (float*)p;
}

extern "C" void kernel_launch(void* const* d_in, const int* in_sizes, int n_in,
                              void* d_out, int out_size)
{
    const float* m     = (const float*)d_in[0];
    const float* pair  = (const float*)d_in[1];
    const float* Wq_w  = (const float*)d_in[2];
    const float* Wkv_w = (const float*)d_in[3];
    const float* Wo_w  = (const float*)d_in[4];
    const float* bo_w  = (const float*)d_in[5];
    const float* Wq_h  = (const float*)d_in[6];
    const float* Wkv_h = (const float*)d_in[7];
    const float* Wo_h  = (const float*)d_in[8];
    const float* bo_h  = (const float*)d_in[9];
    const float* ln_g  = (const float*)d_in[10];
    const float* ln_b  = (const float*)d_in[11];
    const float* Wpair = (const float*)d_in[12];
    const float* Wsq   = (const float*)d_in[13];
    const float* bsq   = (const float*)d_in[14];
    const float* Wsk   = (const float*)d_in[15];
    const float* bsk   = (const float*)d_in[16];
    float* out = (float*)d_out;

    float* Q     = sym(g_Q);
    float* K     = sym(g_K);
    float* V     = sym(g_V);
    float* CW    = sym(g_CW);
    float* CH    = sym(g_CH);
    float* KS    = sym(g_KS);
    float* QS    = sym(g_QS);
    float* TIE   = sym(g_TIE);
    float* DOTS  = sym(g_DOTS);
    float* DOTS2 = sym(g_DOTS2);
    float* PB    = sym(g_PB);
    float* ATT   = sym(g_ATT);
    float* WtQw  = sym(g_WtQw);
    float* WtKVw = sym(g_WtKVw);
    float* WtOw  = sym(g_WtOw);
    float* WtQh  = sym(g_WtQh);
    float* WtKVh = sym(g_WtKVh);
    float* WtOh  = sym(g_WtOh);
    float* WtSq  = sym(g_WtSq);
    float* WtSk  = sym(g_WtSk);

    const dim3 tb(32, 8);
    transpose_k<<<dim3(16, 4), tb>>>(Wq_w,  WtQw,  DDIM,   INNERD);
    transpose_k<<<dim3(32, 4), tb>>>(Wkv_w, WtKVw, DDIM,   2 * INNERD);
    transpose_k<<<dim3(4, 16), tb>>>(Wo_w,  WtOw,  INNERD, DDIM);
    transpose_k<<<dim3(16, 4), tb>>>(Wq_h,  WtQh,  DDIM,   INNERD);
    transpose_k<<<dim3(32, 4), tb>>>(Wkv_h, WtKVh, DDIM,   2 * INNERD);
    transpose_k<<<dim3(4, 16), tb>>>(Wo_h,  WtOh,  INNERD, DDIM);
    transpose_k<<<dim3(4, 4),  tb>>>(Wsq,   WtSq,  DDIM,   DDIM);
    transpose_k<<<dim3(4, 4),  tb>>>(Wsk,   WtSk,  DDIM,   DDIM);

    const dim3 gBig(4, 384);
    const dim3 gD  (1, 384);

    // ---- width (column) attention ----
    gemm_tc<<<gBig, 256>>>(m, DDIM, WtQw,               nullptr, Q, INNERD, DDIM, 1.f, 0.f);
    gemm_tc<<<gBig, 256>>>(m, DDIM, WtKVw,              nullptr, K, INNERD, DDIM, 1.f, 0.f);
    gemm_tc<<<gBig, 256>>>(m, DDIM, WtKVw + 512 * DDIM, nullptr, V, INNERD, DDIM, 1.f, 0.f);
    col_attn_k<<<LL * HHEADS, 128>>>(Q, K, V, CW);

    // ---- height (row) attention ----
    gemm_tc<<<gBig, 256>>>(m, DDIM, WtQh,               nullptr, Q, INNERD, DDIM, 1.f, 0.f);
    gemm_tc<<<gBig, 256>>>(m, DDIM, WtKVh,              nullptr, K, INNERD, DDIM, 1.f, 0.f);
    gemm_tc<<<gBig, 256>>>(m, DDIM, WtKVh + 512 * DDIM, nullptr, V, INNERD, DDIM, 1.f, 0.f);

    gemm_tc<<<dim3(1, 3), 256>>>(m, DDIM, WtSq, bsq, QS, DDIM, DDIM, 1.f, 0.f);
    gemm_tc<<<gD, 256>>>(m, DDIM, WtSk, bsk, KS, DDIM, DDIM, 1.f, 0.f);

    tie_k<<<LL * HHEADS, 128>>>(QS, KS, TIE);
    dots_tc<<<dim3(3, 3, 16), 256>>>(TIE, Q, K, DOTS, DOTS2);
    pb_k<<<LL * LL / 4, 128>>>(pair, ln_g, ln_b, Wpair, PB);
    softh_k<<<dim3(LL, HHEADS), 128>>>(DOTS, DOTS2, PB, ATT);
    oh_tc<<<dim3(3, RR * HHEADS), 256>>>(ATT, V, CH);

    // ---- fused output ----
    gemm_tc<<<gD, 256>>>(CW, INNERD, WtOw, bo_w, out, DDIM, INNERD, 0.5f, 0.f);
    gemm_tc<<<gD, 256>>>(CH, INNERD, WtOh, bo_h, out, DDIM, INNERD, 0.5f, 1.f);
}

// round 6
// speedup vs baseline: 2.5748x; 1.3234x over previous
#include <cuda_runtime.h>
#include <cstdint>

#define RR     128
#define LL     384
#define DDIM   128
#define HHEADS 8
#define DHEAD  64
#define DPAIR  128
#define INNERD 512
#define ML     (RR*LL)
#define DHW    16

// ---------------- scratch ----------
__device__ float g_Mt[ML*DDIM];             // m pre-converted to tf32 bits
__device__ float g_Q [ML*INNERD];
__device__ float g_K [ML*INNERD];
__device__ float g_V [ML*INNERD];
__device__ float g_CW[ML*INNERD];
__device__ float g_CH[ML*INNERD];
__device__ float g_KS[ML*DDIM];
__device__ float g_QS[LL*DDIM];
__device__ float g_TIE  [HHEADS*RR*LL];     // [h][r][l]
__device__ float g_DOTS [HHEADS*LL*LL];
__device__ float g_DOTS2[HHEADS*LL*LL];
__device__ float g_PB  [LL*LL*HHEADS];
__device__ float g_ATT [HHEADS*LL*LL];
__device__ float g_WtQw [INNERD*DDIM];
__device__ float g_WtKVw[2*INNERD*DDIM];
__device__ float g_WtOw [DDIM*INNERD];
__device__ float g_WtQh [INNERD*DDIM];
__device__ float g_WtKVh[2*INNERD*DDIM];
__device__ float g_WtOh [DDIM*INNERD];
__device__ float g_WtSq [DDIM*DDIM];
__device__ float g_WtSk [DDIM*DDIM];

// ---------------------------------------------------------------------------
__device__ __forceinline__ void mma_tf32(float* d, const uint32_t* a, const uint32_t* b) {
    asm volatile(
        "mma.sync.aligned.m16n8k8.row.col.f32.tf32.tf32.f32 "
        "{%0,%1,%2,%3}, {%4,%5,%6,%7}, {%8,%9}, {%0,%1,%2,%3};"
        : "+f"(d[0]), "+f"(d[1]), "+f"(d[2]), "+f"(d[3])
        : "r"(a[0]), "r"(a[1]), "r"(a[2]), "r"(a[3]), "r"(b[0]), "r"(b[1]));
}
__device__ __forceinline__ uint32_t f2tf32(float v) {
    uint32_t o;
    asm("cvt.rna.tf32.f32 %0, %1;" : "=r"(o) : "f"(v));
    return o;
}
__device__ __forceinline__ float tf32f(float v) {
    return __uint_as_float(f2tf32(v));
}
__device__ __forceinline__ uint32_t smem_u32(const void* p) {
    uint32_t a;
    asm("{ .reg .u64 t; cvta.to.shared.u64 t, %1; cvt.u32.u64 %0, t; }"
        : "=r"(a) : "l"(p));
    return a;
}
__device__ __forceinline__ void cp16(uint32_t dst, const void* src) {
    asm volatile("cp.async.ca.shared.global [%0], [%1], 16;" :: "r"(dst), "l"(src));
}

// ---------------------------------------------------------------------------
// m -> tf32 bits
// ---------------------------------------------------------------------------
__global__ __launch_bounds__(256) void cvt_k(const float* __restrict__ s,
                                             float* __restrict__ d)
{
    int i = (blockIdx.x * 256 + threadIdx.x) * 4;
    float4 v = *(const float4*)&s[i];
    v.x = tf32f(v.x); v.y = tf32f(v.y); v.z = tf32f(v.z); v.w = tf32f(v.w);
    *(float4*)&d[i] = v;
}

// ---------------------------------------------------------------------------
// Weight transpose (+tf32 round): Wt[n*K + k] = tf32(W[k*N + n])
// ---------------------------------------------------------------------------
__global__ void transpose_k(const float* __restrict__ W, float* __restrict__ Wt,
                            int K, int N)
{
    __shared__ float tile[32][33];
    int kb = blockIdx.y * 32, nb = blockIdx.x * 32;
    int tx = threadIdx.x, ty = threadIdx.y;
#pragma unroll
    for (int i = 0; i < 32; i += 8)
        tile[ty + i][tx] = W[(size_t)(kb + ty + i) * N + nb + tx];
    __syncthreads();
#pragma unroll
    for (int i = 0; i < 32; i += 8)
        Wt[(size_t)(nb + ty + i) * K + kb + tx] = tf32f(tile[tx][ty + i]);
}

// ---------------------------------------------------------------------------
// tf32 tensor-core GEMM, cp.async double-buffered. Inputs pre-rounded to tf32.
// Block 128x128, BK=16, 8 warps (4x2), warp 32x64.
// ---------------------------------------------------------------------------
__global__ __launch_bounds__(256) void gemm_tc(
    const float* __restrict__ X, int ldx,
    const float* __restrict__ Wt,
    const float* __restrict__ bias,
    float* __restrict__ C, int ldc,
    int K, float alpha, float beta)
{
    __shared__ float As[2][2560];   // [buf][128*20]
    __shared__ float Bs[2][2560];

    const int t    = threadIdx.x;
    const int lane = t & 31;
    const int wid  = t >> 5;
    const int wm   = (wid & 3) * 32;
    const int wn   = (wid >> 2) * 64;
    const int row0 = blockIdx.y * 128;
    const int col0 = blockIdx.x * 128;
    const int lr = t >> 2;
    const int lc = (t & 3) * 4;
    const uint32_t asu = smem_u32(As);
    const uint32_t bsu = smem_u32(Bs);

    float acc[2][8][4];
#pragma unroll
    for (int mt = 0; mt < 2; mt++)
#pragma unroll
        for (int nt = 0; nt < 8; nt++)
#pragma unroll
            for (int i = 0; i < 4; i++) acc[mt][nt][i] = 0.f;

    auto issue = [&](int k0, int buf) {
#pragma unroll
        for (int half = 0; half < 2; half++) {
            int r = lr + half * 64;
            cp16(asu + (uint32_t)(buf * 2560 + r * 20 + lc) * 4,
                 &X[(size_t)(row0 + r) * ldx + k0 + lc]);
            cp16(bsu + (uint32_t)(buf * 2560 + r * 20 + lc) * 4,
                 &Wt[(size_t)(col0 + r) * K + k0 + lc]);
        }
        asm volatile("cp.async.commit_group;");
    };

    const int ntile = K >> 4;
    issue(0, 0);
    for (int i = 0; i < ntile; i++) {
        if (i + 1 < ntile) {
            issue((i + 1) << 4, (i + 1) & 1);
            asm volatile("cp.async.wait_group 1;");
        } else {
            asm volatile("cp.async.wait_group 0;");
        }
        __syncthreads();
        const float* A = As[i & 1];
        const float* B = Bs[i & 1];
#pragma unroll
        for (int ks = 0; ks < 16; ks += 8) {
            uint32_t af[2][4];
            const int fr = lane >> 2;
            const int fc = ks + (lane & 3);
#pragma unroll
            for (int mt = 0; mt < 2; mt++) {
                int r = wm + mt * 16 + fr;
                af[mt][0] = __float_as_uint(A[r * 20 + fc]);
                af[mt][1] = __float_as_uint(A[(r + 8) * 20 + fc]);
                af[mt][2] = __float_as_uint(A[r * 20 + fc + 4]);
                af[mt][3] = __float_as_uint(A[(r + 8) * 20 + fc + 4]);
            }
#pragma unroll
            for (int nt = 0; nt < 8; nt++) {
                uint32_t bf[2];
                int n = wn + nt * 8 + fr;
                bf[0] = __float_as_uint(B[n * 20 + fc]);
                bf[1] = __float_as_uint(B[n * 20 + fc + 4]);
                mma_tf32(acc[0][nt], af[0], bf);
                mma_tf32(acc[1][nt], af[1], bf);
            }
        }
        __syncthreads();
    }

#pragma unroll
    for (int mt = 0; mt < 2; mt++) {
#pragma unroll
        for (int nt = 0; nt < 8; nt++) {
            int rg = row0 + wm + mt * 16 + (lane >> 2);
            int cg = col0 + wn + nt * 8 + (lane & 3) * 2;
            float bx = 0.f, by = 0.f;
            if (bias) { bx = bias[cg]; by = bias[cg + 1]; }
#pragma unroll
            for (int half = 0; half < 2; half++) {
                int r = rg + half * 8;
                float vx = alpha * (acc[mt][nt][half * 2 + 0] + bx);
                float vy = alpha * (acc[mt][nt][half * 2 + 1] + by);
                float2* cp = (float2*)&C[(size_t)r * ldc + cg];
                if (beta != 0.f) {
                    float2 o = *cp;
                    vx += beta * o.x; vy += beta * o.y;
                }
                float2 v = {vx, vy};
                *cp = v;
            }
        }
    }
}

// ---------------------------------------------------------------------------
// Tensor-core column attention. One block per (l,h). 256 threads = 8 warps,
// each warp owns 16 query rows x all 128 key cols.
// Dynamic SMEM: Qs[128*68] | Ks[128*68] (P[128*132] overlaps Qs+Ks) | Vt[64*132]
// ---------------------------------------------------------------------------
__global__ __launch_bounds__(256, 2) void col_attn_tc(
    const float* __restrict__ Q, const float* __restrict__ K,
    const float* __restrict__ V, float* __restrict__ CW)
{
    extern __shared__ float sm[];
    float* Qs = sm;                    // [128][68]
    float* Ks = sm + 128 * 68;         // [128][68]
    float* P  = sm;                    // [128][132] (overlap, used after S)
    float* Vt = sm + 2 * 128 * 68;     // [64][132]

    const int l = blockIdx.x >> 3;
    const int h = blockIdx.x & 7;
    const int t = threadIdx.x;
    const int lane = t & 31;
    const int wid  = t >> 5;
    const int wm   = wid * 16;
    const int fr   = lane >> 2;
    const int q2   = (lane & 3) * 2;
    const size_t RS = (size_t)LL * INNERD;

    const float* qb = Q + (size_t)l * INNERD + h * DHEAD;
    const float* kb = K + (size_t)l * INNERD + h * DHEAD;
    const float* vb = V + (size_t)l * INNERD + h * DHEAD;

    // stage Q, K (tf32 bits)
    for (int idx = t; idx < 2048; idx += 256) {
        int row = idx >> 4, c4 = (idx & 15) * 4;
        float4 a = *(const float4*)(qb + row * RS + c4);
        float4 b = *(const float4*)(kb + row * RS + c4);
        a.x = tf32f(a.x); a.y = tf32f(a.y); a.z = tf32f(a.z); a.w = tf32f(a.w);
        b.x = tf32f(b.x); b.y = tf32f(b.y); b.z = tf32f(b.z); b.w = tf32f(b.w);
        *(float4*)&Qs[row * 68 + c4] = a;
        *(float4*)&Ks[row * 68 + c4] = b;
    }
    __syncthreads();

    // S = Q K^T  (per-warp: 16 rows x 128 cols)
    float acc[16][4];
#pragma unroll
    for (int nt = 0; nt < 16; nt++)
#pragma unroll
        for (int i = 0; i < 4; i++) acc[nt][i] = 0.f;

#pragma unroll
    for (int ks = 0; ks < 64; ks += 8) {
        const int fc = ks + (lane & 3);
        uint32_t af[4];
        af[0] = __float_as_uint(Qs[(wm + fr) * 68 + fc]);
        af[1] = __float_as_uint(Qs[(wm + fr + 8) * 68 + fc]);
        af[2] = __float_as_uint(Qs[(wm + fr) * 68 + fc + 4]);
        af[3] = __float_as_uint(Qs[(wm + fr + 8) * 68 + fc + 4]);
#pragma unroll
        for (int nt = 0; nt < 16; nt++) {
            uint32_t bf[2];
            bf[0] = __float_as_uint(Ks[(nt * 8 + fr) * 68 + fc]);
            bf[1] = __float_as_uint(Ks[(nt * 8 + fr) * 68 + fc + 4]);
            mma_tf32(acc[nt], af, bf);
        }
    }

    // softmax over j (rows wm+fr and wm+fr+8), scale 0.125
    float mx0 = -1e30f, mx1 = -1e30f;
#pragma unroll
    for (int nt = 0; nt < 16; nt++) {
        mx0 = fmaxf(mx0, fmaxf(acc[nt][0], acc[nt][1]));
        mx1 = fmaxf(mx1, fmaxf(acc[nt][2], acc[nt][3]));
    }
    mx0 = fmaxf(mx0, __shfl_xor_sync(0xffffffffu, mx0, 1));
    mx0 = fmaxf(mx0, __shfl_xor_sync(0xffffffffu, mx0, 2));
    mx1 = fmaxf(mx1, __shfl_xor_sync(0xffffffffu, mx1, 1));
    mx1 = fmaxf(mx1, __shfl_xor_sync(0xffffffffu, mx1, 2));
    float s0 = 0.f, s1 = 0.f;
#pragma unroll
    for (int nt = 0; nt < 16; nt++) {
        acc[nt][0] = __expf(0.125f * (acc[nt][0] - mx0)); s0 += acc[nt][0];
        acc[nt][1] = __expf(0.125f * (acc[nt][1] - mx0)); s0 += acc[nt][1];
        acc[nt][2] = __expf(0.125f * (acc[nt][2] - mx1)); s1 += acc[nt][2];
        acc[nt][3] = __expf(0.125f * (acc[nt][3] - mx1)); s1 += acc[nt][3];
    }
    s0 += __shfl_xor_sync(0xffffffffu, s0, 1);
    s0 += __shfl_xor_sync(0xffffffffu, s0, 2);
    s1 += __shfl_xor_sync(0xffffffffu, s1, 1);
    s1 += __shfl_xor_sync(0xffffffffu, s1, 2);

    __syncthreads();   // Qs/Ks dead — P may overwrite

    // write P (tf32 bits)
#pragma unroll
    for (int nt = 0; nt < 16; nt++) {
        float2 p0 = {tf32f(acc[nt][0]), tf32f(acc[nt][1])};
        float2 p1 = {tf32f(acc[nt][2]), tf32f(acc[nt][3])};
        *(float2*)&P[(wm + fr) * 132 + nt * 8 + q2]     = p0;
        *(float2*)&P[(wm + fr + 8) * 132 + nt * 8 + q2] = p1;
    }
    // stage V transposed: Vt[d][j] (tf32 bits)
    for (int idx = t; idx < 2048; idx += 256) {
        int j = idx >> 4, c4 = (idx & 15) * 4;
        float4 v = *(const float4*)(vb + j * RS + c4);
        Vt[(c4 + 0) * 132 + j] = tf32f(v.x);
        Vt[(c4 + 1) * 132 + j] = tf32f(v.y);
        Vt[(c4 + 2) * 132 + j] = tf32f(v.z);
        Vt[(c4 + 3) * 132 + j] = tf32f(v.w);
    }
    __syncthreads();

    // O = P V  (per-warp: 16 rows x 64 d)
    float o[8][4];
#pragma unroll
    for (int nt = 0; nt < 8; nt++)
#pragma unroll
        for (int i = 0; i < 4; i++) o[nt][i] = 0.f;

#pragma unroll
    for (int ks = 0; ks < 128; ks += 8) {
        const int fc = ks + (lane & 3);
        uint32_t af[4];
        af[0] = __float_as_uint(P[(wm + fr) * 132 + fc]);
        af[1] = __float_as_uint(P[(wm + fr + 8) * 132 + fc]);
        af[2] = __float_as_uint(P[(wm + fr) * 132 + fc + 4]);
        af[3] = __float_as_uint(P[(wm + fr + 8) * 132 + fc + 4]);
#pragma unroll
        for (int nt = 0; nt < 8; nt++) {
            uint32_t bf[2];
            bf[0] = __float_as_uint(Vt[(nt * 8 + fr) * 132 + fc]);
            bf[1] = __float_as_uint(Vt[(nt * 8 + fr) * 132 + fc + 4]);
            mma_tf32(o[nt], af, bf);
        }
    }

    const float inv0 = 1.f / s0, inv1 = 1.f / s1;
    float* ow = CW + (size_t)l * INNERD + h * DHEAD;
#pragma unroll
    for (int nt = 0; nt < 8; nt++) {
        int cg = nt * 8 + q2;
        float2 v0 = {tf32f(o[nt][0] * inv0), tf32f(o[nt][1] * inv0)};
        float2 v1 = {tf32f(o[nt][2] * inv1), tf32f(o[nt][3] * inv1)};
        *(float2*)(ow + (size_t)(wm + fr) * RS + cg)     = v0;
        *(float2*)(ow + (size_t)(wm + fr + 8) * RS + cg) = v1;
    }
}

// ---------------------------------------------------------------------------
// dots_tc (unchanged from round 5)
// ---------------------------------------------------------------------------
__global__ __launch_bounds__(256) void dots_tc(
    const float* __restrict__ TIE,
    const float* __restrict__ QH, const float* __restrict__ KH,
    float* __restrict__ D1, float* __restrict__ D2)
{
    __shared__ float As[128 * 36];
    __shared__ float Bs[128 * 36];
    __shared__ float wv_s[8 * 128];

    const int t    = threadIdx.x;
    const int lane = t & 31;
    const int wid  = t >> 5;
    const int wm   = (wid & 3) * 32;
    const int wn   = (wid >> 2) * 64;
    const int i0 = blockIdx.y * 128;
    const int j0 = blockIdx.x * 128;
    const int h  = blockIdx.z & 7;
    const int rz = blockIdx.z >> 3;

    float acc[2][8][4];
#pragma unroll
    for (int mt = 0; mt < 2; mt++)
#pragma unroll
        for (int nt = 0; nt < 8; nt++)
#pragma unroll
            for (int i = 0; i < 4; i++) acc[mt][nt][i] = 0.f;

    for (int rb = rz * 64; rb < rz * 64 + 64; rb += 8) {
        __syncthreads();
#pragma unroll
        for (int i = 0; i < 4; i++) {
            int e = t + 256 * i;
            int rr = e >> 7, row = e & 127;
            wv_s[rr * 128 + row] = TIE[((size_t)(h * RR + rb + rr)) * LL + i0 + row];
        }
        __syncthreads();
        for (int rr = 0; rr < 8; rr++) {
            const int r = rb + rr;
            const float* qbase = &QH[((size_t)r * LL + i0) * INNERD + h * DHEAD];
            const float* kbase = &KH[((size_t)r * LL + j0) * INNERD + h * DHEAD];
#pragma unroll
            for (int seg = 0; seg < 2; seg++) {
                const int d0 = seg * 32;
#pragma unroll
                for (int i = 0; i < 4; i++) {
                    int idx = t + 256 * i;
                    int row = idx >> 3, c4 = (idx & 7) * 4;
                    float wv = wv_s[rr * 128 + row];
                    float4 va = *(const float4*)&qbase[(size_t)row * INNERD + d0 + c4];
                    float4 vb = *(const float4*)&kbase[(size_t)row * INNERD + d0 + c4];
                    uint4 ua, ub;
                    ua.x = f2tf32(va.x * wv); ua.y = f2tf32(va.y * wv);
                    ua.z = f2tf32(va.z * wv); ua.w = f2tf32(va.w * wv);
                    ub.x = f2tf32(vb.x); ub.y = f2tf32(vb.y);
                    ub.z = f2tf32(vb.z); ub.w = f2tf32(vb.w);
                    *(uint4*)&As[row * 36 + c4] = ua;
                    *(uint4*)&Bs[row * 36 + c4] = ub;
                }
                __syncthreads();
#pragma unroll
                for (int ks = 0; ks < 32; ks += 8) {
                    uint32_t af[2][4];
                    const int fr = lane >> 2;
                    const int fc = ks + (lane & 3);
#pragma unroll
                    for (int mt = 0; mt < 2; mt++) {
                        int rw = wm + mt * 16 + fr;
                        af[mt][0] = __float_as_uint(As[rw * 36 + fc]);
                        af[mt][1] = __float_as_uint(As[(rw + 8) * 36 + fc]);
                        af[mt][2] = __float_as_uint(As[rw * 36 + fc + 4]);
                        af[mt][3] = __float_as_uint(As[(rw + 8) * 36 + fc + 4]);
                    }
#pragma unroll
                    for (int nt = 0; nt < 8; nt++) {
                        uint32_t bf[2];
                        int n = wn + nt * 8 + fr;
                        bf[0] = __float_as_uint(Bs[n * 36 + fc]);
                        bf[1] = __float_as_uint(Bs[n * 36 + fc + 4]);
                        mma_tf32(acc[0][nt], af[0], bf);
                        mma_tf32(acc[1][nt], af[1], bf);
                    }
                }
                __syncthreads();
            }
        }
    }

    float* OUT = (rz ? D2 : D1) + (size_t)h * LL * LL;
#pragma unroll
    for (int mt = 0; mt < 2; mt++) {
#pragma unroll
        for (int nt = 0; nt < 8; nt++) {
            int rg = i0 + wm + mt * 16 + (lane >> 2);
            int cg = j0 + wn + nt * 8 + (lane & 3) * 2;
#pragma unroll
            for (int half = 0; half < 2; half++) {
                int rw = rg + half * 8;
                float2 v = {0.125f * acc[mt][nt][half * 2 + 0],
                            0.125f * acc[mt][nt][half * 2 + 1]};
                *(float2*)&OUT[(size_t)rw * LL + cg] = v;
            }
        }
    }
}

// ---------------------------------------------------------------------------
// oh_tc (round 5 + tf32-rounded CH stores)
// ---------------------------------------------------------------------------
__global__ __launch_bounds__(256) void oh_tc(
    const float* __restrict__ ATT, const float* __restrict__ VH,
    float* __restrict__ CH)
{
    __shared__ float As[128 * 20];
    __shared__ float Bs[64 * 20];

    const int t    = threadIdx.x;
    const int lane = t & 31;
    const int wid  = t >> 5;
    const int wm   = (wid & 3) * 32;
    const int wn   = (wid >> 2) * 32;
    const int i0 = blockIdx.x * 128;
    const int r  = blockIdx.y >> 3;
    const int h  = blockIdx.y & 7;

    float acc[2][4][4];
#pragma unroll
    for (int mt = 0; mt < 2; mt++)
#pragma unroll
        for (int nt = 0; nt < 4; nt++)
#pragma unroll
            for (int i = 0; i < 4; i++) acc[mt][nt][i] = 0.f;

    for (int k0 = 0; k0 < LL; k0 += 16) {
#pragma unroll
        for (int i = 0; i < 2; i++) {
            int idx = t + 256 * i;
            int row = idx >> 2, c4 = (idx & 3) * 4;
            float4 va = *(const float4*)&ATT[((size_t)h * LL + i0 + row) * LL + k0 + c4];
            uint4 ua;
            ua.x = f2tf32(va.x); ua.y = f2tf32(va.y);
            ua.z = f2tf32(va.z); ua.w = f2tf32(va.w);
            *(uint4*)&As[row * 20 + c4] = ua;
        }
        {
            int kr = t >> 4;
            int dc = (t & 15) * 4;
            float4 vb = *(const float4*)&VH[((size_t)(r * LL + k0 + kr)) * INNERD + h * DHEAD + dc];
            Bs[(dc + 0) * 20 + kr] = tf32f(vb.x);
            Bs[(dc + 1) * 20 + kr] = tf32f(vb.y);
            Bs[(dc + 2) * 20 + kr] = tf32f(vb.z);
            Bs[(dc + 3) * 20 + kr] = tf32f(vb.w);
        }
        __syncthreads();
#pragma unroll
        for (int ks = 0; ks < 16; ks += 8) {
            uint32_t af[2][4];
            const int fr = lane >> 2;
            const int fc = ks + (lane & 3);
#pragma unroll
            for (int mt = 0; mt < 2; mt++) {
                int rw = wm + mt * 16 + fr;
                af[mt][0] = __float_as_uint(As[rw * 20 + fc]);
                af[mt][1] = __float_as_uint(As[(rw + 8) * 20 + fc]);
                af[mt][2] = __float_as_uint(As[rw * 20 + fc + 4]);
                af[mt][3] = __float_as_uint(As[(rw + 8) * 20 + fc + 4]);
            }
#pragma unroll
            for (int nt = 0; nt < 4; nt++) {
                uint32_t bf[2];
                int n = wn + nt * 8 + fr;
                bf[0] = __float_as_uint(Bs[n * 20 + fc]);
                bf[1] = __float_as_uint(Bs[n * 20 + fc + 4]);
                mma_tf32(acc[0][nt], af[0], bf);
                mma_tf32(acc[1][nt], af[1], bf);
            }
        }
        __syncthreads();
    }

#pragma unroll
    for (int mt = 0; mt < 2; mt++) {
#pragma unroll
        for (int nt = 0; nt < 4; nt++) {
            int rloc = i0 + wm + mt * 16 + (lane >> 2);
            int cg   = wn + nt * 8 + (lane & 3) * 2;
#pragma unroll
            for (int half = 0; half < 2; half++) {
                int rw = rloc + half * 8;
                float2 v = {tf32f(acc[mt][nt][half * 2 + 0]),
                            tf32f(acc[mt][nt][half * 2 + 1])};
                *(float2*)&CH[((size_t)(r * LL + rw)) * INNERD + h * DHEAD + cg] = v;
            }
        }
    }
}

// ---------------------------------------------------------------------------
// Row-tie weights -> TIE[h][r][l]
// ---------------------------------------------------------------------------
__global__ __launch_bounds__(128) void tie_k(
    const float* __restrict__ QS, const float* __restrict__ KS,
    float* __restrict__ TIE)
{
    const int l = blockIdx.x >> 3;
    const int h = blockIdx.x & 7;
    const int r = threadIdx.x;
    const float* q = &QS[l * DDIM + h * DHW];
    const float* k = &KS[((size_t)r * LL + l) * DDIM + h * DHW];
    float s = 0.f;
#pragma unroll
    for (int d = 0; d < DHW; d++) s += q[d] * k[d];
    s *= 0.25f;

    __shared__ float red[128];
    red[r] = s; __syncthreads();
    for (int o = 64; o; o >>= 1) { if (r < o) red[r] = fmaxf(red[r], red[r + o]); __syncthreads(); }
    float m = red[0]; __syncthreads();
    float e = __expf(s - m);
    red[r] = e; __syncthreads();
    for (int o = 64; o; o >>= 1) { if (r < o) red[r] += red[r + o]; __syncthreads(); }
    TIE[((size_t)h * RR + r) * LL + l] = e / red[0];
}

// ---------------------------------------------------------------------------
// Pair bias
// ---------------------------------------------------------------------------
__global__ __launch_bounds__(128) void pb_k(
    const float* __restrict__ pair, const float* __restrict__ gam,
    const float* __restrict__ bet, const float* __restrict__ Wp,
    float* __restrict__ PB)
{
    const int w    = threadIdx.x >> 5;
    const int lane = threadIdx.x & 31;
    const int pid  = blockIdx.x * 4 + w;
    float4 x4 = *(const float4*)&pair[(size_t)pid * DPAIR + lane * 4];
    float x[4] = {x4.x, x4.y, x4.z, x4.w};
    float s1 = x[0] + x[1] + x[2] + x[3];
    float s2 = x[0]*x[0] + x[1]*x[1] + x[2]*x[2] + x[3]*x[3];
#pragma unroll
    for (int o = 16; o; o >>= 1) {
        s1 += __shfl_xor_sync(0xffffffffu, s1, o);
        s2 += __shfl_xor_sync(0xffffffffu, s2, o);
    }
    float mu  = s1 * (1.f / DPAIR);
    float var = s2 * (1.f / DPAIR) - mu * mu;
    float inv = rsqrtf(var + 1e-5f);

    float acc[8];
#pragma unroll
    for (int hh = 0; hh < 8; hh++) acc[hh] = 0.f;
#pragma unroll
    for (int u = 0; u < 4; u++) {
        int c = lane * 4 + u;
        float nx = (x[u] - mu) * inv * gam[c] + bet[c];
#pragma unroll
        for (int hh = 0; hh < 8; hh++) acc[hh] += nx * Wp[c * 8 + hh];
    }
#pragma unroll
    for (int o = 16; o; o >>= 1)
#pragma unroll
        for (int hh = 0; hh < 8; hh++) acc[hh] += __shfl_xor_sync(0xffffffffu, acc[hh], o);
    if (lane == 0) {
#pragma unroll
        for (int hh = 0; hh < 8; hh++) PB[(size_t)pid * 8 + hh] = acc[hh];
    }
}

// ---------------------------------------------------------------------------
// softmax over dots1+dots2+pair bias
// ---------------------------------------------------------------------------
__global__ __launch_bounds__(128) void softh_k(
    const float* __restrict__ D1, const float* __restrict__ D2,
    const float* __restrict__ PB, float* __restrict__ ATT)
{
    const int i = blockIdx.x;
    const int h = blockIdx.y;
    const int t = threadIdx.x;
    const float* dp1 = &D1[((size_t)h * LL + i) * LL];
    const float* dp2 = &D2[((size_t)h * LL + i) * LL];
    float x[3];
#pragma unroll
    for (int u = 0; u < 3; u++) {
        int j = t + u * 128;
        x[u] = dp1[j] + dp2[j] + PB[((size_t)i * LL + j) * 8 + h];
    }
    __shared__ float red[128];
    float lm = fmaxf(fmaxf(x[0], x[1]), x[2]);
    red[t] = lm; __syncthreads();
    for (int o = 64; o; o >>= 1) { if (t < o) red[t] = fmaxf(red[t], red[t + o]); __syncthreads(); }
    float mx = red[0]; __syncthreads();
    float e[3], ls = 0.f;
#pragma unroll
    for (int u = 0; u < 3; u++) { e[u] = __expf(x[u] - mx); ls += e[u]; }
    red[t] = ls; __syncthreads();
    for (int o = 64; o; o >>= 1) { if (t < o) red[t] += red[t + o]; __syncthreads(); }
    float inv = 1.f / red[0];
    float* ap = &ATT[((size_t)h * LL + i) * LL];
#pragma unroll
    for (int u = 0; u < 3; u++) ap[t + u * 128] = e[u] * inv;
}

// ---------------------------------------------------------------------------
static float* sym(const void* s) {
    void* p = nullptr;
    cudaGetSymbolAddress(&p, s);
    return (float*)p;
}

extern "C" void kernel_launch(void* const* d_in, const int* in_sizes, int n_in,
                              void* d_out, int out_size)
{
    const float* m     = (const float*)d_in[0];
    const float* pair  = (const float*)d_in[1];
    const float* Wq_w  = (const float*)d_in[2];
    const float* Wkv_w = (const float*)d_in[3];
    const float* Wo_w  = (const float*)d_in[4];
    const float* bo_w  = (const float*)d_in[5];
    const float* Wq_h  = (const float*)d_in[6];
    const float* Wkv_h = (const float*)d_in[7];
    const float* Wo_h  = (const float*)d_in[8];
    const float* bo_h  = (const float*)d_in[9];
    const float* ln_g  = (const float*)d_in[10];
    const float* ln_b  = (const float*)d_in[11];
    const float* Wpair = (const float*)d_in[12];
    const float* Wsq   = (const float*)d_in[13];
    const float* bsq   = (const float*)d_in[14];
    const float* Wsk   = (const float*)d_in[15];
    const float* bsk   = (const float*)d_in[16];
    float* out = (float*)d_out;

    float* Mt    = sym(g_Mt);
    float* Q     = sym(g_Q);
    float* K     = sym(g_K);
    float* V     = sym(g_V);
    float* CW    = sym(g_CW);
    float* CH    = sym(g_CH);
    float* KS    = sym(g_KS);
    float* QS    = sym(g_QS);
    float* TIE   = sym(g_TIE);
    float* DOTS  = sym(g_DOTS);
    float* DOTS2 = sym(g_DOTS2);
    float* PB    = sym(g_PB);
    float* ATT   = sym(g_ATT);
    float* WtQw  = sym(g_WtQw);
    float* WtKVw = sym(g_WtKVw);
    float* WtOw  = sym(g_WtOw);
    float* WtQh  = sym(g_WtQh);
    float* WtKVh = sym(g_WtKVh);
    float* WtOh  = sym(g_WtOh);
    float* WtSq  = sym(g_WtSq);
    float* WtSk  = sym(g_WtSk);

    // enable 103KB dynamic smem for col_attn_tc (idempotent)
    static int attr_set = 0;
    const int CA_SMEM = (2 * 128 * 68 + 64 * 132) * 4;
    cudaFuncSetAttribute(col_attn_tc, cudaFuncAttributeMaxDynamicSharedMemorySize, CA_SMEM);

    const dim3 tb(32, 8);
    cvt_k<<<ML * DDIM / 1024, 256>>>(m, Mt);
    transpose_k<<<dim3(16, 4), tb>>>(Wq_w,  WtQw,  DDIM,   INNERD);
    transpose_k<<<dim3(32, 4), tb>>>(Wkv_w, WtKVw, DDIM,   2 * INNERD);
    transpose_k<<<dim3(4, 16), tb>>>(Wo_w,  WtOw,  INNERD, DDIM);
    transpose_k<<<dim3(16, 4), tb>>>(Wq_h,  WtQh,  DDIM,   INNERD);
    transpose_k<<<dim3(32, 4), tb>>>(Wkv_h, WtKVh, DDIM,   2 * INNERD);
    transpose_k<<<dim3(4, 16), tb>>>(Wo_h,  WtOh,  INNERD, DDIM);
    transpose_k<<<dim3(4, 4),  tb>>>(Wsq,   WtSq,  DDIM,   DDIM);
    transpose_k<<<dim3(4, 4),  tb>>>(Wsk,   WtSk,  DDIM,   DDIM);

    const dim3 gBig(4, 384);
    const dim3 gD  (1, 384);

    // ---- width (column) attention ----
    gemm_tc<<<gBig, 256>>>(Mt, DDIM, WtQw,               nullptr, Q, INNERD, DDIM, 1.f, 0.f);
    gemm_tc<<<gBig, 256>>>(Mt, DDIM, WtKVw,              nullptr, K, INNERD, DDIM, 1.f, 0.f);
    gemm_tc<<<gBig, 256>>>(Mt, DDIM, WtKVw + 512 * DDIM, nullptr, V, INNERD, DDIM, 1.f, 0.f);
    col_attn_tc<<<LL * HHEADS, 256, CA_SMEM>>>(Q, K, V, CW);

    // ---- height (row) attention ----
    gemm_tc<<<gBig, 256>>>(Mt, DDIM, WtQh,               nullptr, Q, INNERD, DDIM, 1.f, 0.f);
    gemm_tc<<<gBig, 256>>>(Mt, DDIM, WtKVh,              nullptr, K, INNERD, DDIM, 1.f, 0.f);
    gemm_tc<<<gBig, 256>>>(Mt, DDIM, WtKVh + 512 * DDIM, nullptr, V, INNERD, DDIM, 1.f, 0.f);

    gemm_tc<<<dim3(1, 3), 256>>>(Mt, DDIM, WtSq, bsq, QS, DDIM, DDIM, 1.f, 0.f);
    gemm_tc<<<gD, 256>>>(Mt, DDIM, WtSk, bsk, KS, DDIM, DDIM, 1.f, 0.f);

    tie_k<<<LL * HHEADS, 128>>>(QS, KS, TIE);
    dots_tc<<<dim3(3, 3, 16), 256>>>(TIE, Q, K, DOTS, DOTS2);
    pb_k<<<LL * LL / 4, 128>>>(pair, ln_g, ln_b, Wpair, PB);
    softh_k<<<dim3(LL, HHEADS), 128>>>(DOTS, DOTS2, PB, ATT);
    oh_tc<<<dim3(3, RR * HHEADS), 256>>>(ATT, V, CH);

    // ---- fused output ----
    gemm_tc<<<gD, 256>>>(CW, INNERD, WtOw, bo_w, out, DDIM, INNERD, 0.5f, 0.f);
    gemm_tc<<<gD, 256>>>(CH, INNERD, WtOh, bo_h, out, DDIM, INNERD, 0.5f, 1.f);
}

// round 7
// speedup vs baseline: 2.5914x; 1.0064x over previous
#include <cuda_runtime.h>
#include <cstdint>

#define RR     128
#define LL     384
#define DDIM   128
#define HHEADS 8
#define DHEAD  64
#define DPAIR  128
#define INNERD 512
#define ML     (RR*LL)
#define DHW    16

// ---------------- scratch ----------
__device__ float g_Mt[ML*DDIM];             // m pre-converted to tf32 bits
__device__ float g_Q [ML*INNERD];
__device__ float g_K [ML*INNERD];
__device__ float g_V [ML*INNERD];
__device__ float g_CW[ML*INNERD];
__device__ float g_CH[ML*INNERD];
__device__ float g_KS[ML*DDIM];
__device__ float g_QS[LL*DDIM];
__device__ float g_TIE  [HHEADS*RR*LL];     // [h][r][l]
__device__ float g_DOTS [HHEADS*LL*LL];
__device__ float g_DOTS2[HHEADS*LL*LL];
__device__ float g_PB  [LL*LL*HHEADS];
__device__ float g_ATT [HHEADS*LL*LL];
__device__ float g_WtQw [INNERD*DDIM];
__device__ float g_WtKVw[2*INNERD*DDIM];
__device__ float g_WtOw [DDIM*INNERD];
__device__ float g_WtQh [INNERD*DDIM];
__device__ float g_WtKVh[2*INNERD*DDIM];
__device__ float g_WtOh [DDIM*INNERD];
__device__ float g_WtSq [DDIM*DDIM];
__device__ float g_WtSk [DDIM*DDIM];

// ---------------------------------------------------------------------------
__device__ __forceinline__ void mma_tf32(float* d, const uint32_t* a, const uint32_t* b) {
    asm volatile(
        "mma.sync.aligned.m16n8k8.row.col.f32.tf32.tf32.f32 "
        "{%0,%1,%2,%3}, {%4,%5,%6,%7}, {%8,%9}, {%0,%1,%2,%3};"
        : "+f"(d[0]), "+f"(d[1]), "+f"(d[2]), "+f"(d[3])
        : "r"(a[0]), "r"(a[1]), "r"(a[2]), "r"(a[3]), "r"(b[0]), "r"(b[1]));
}
__device__ __forceinline__ uint32_t f2tf32(float v) {
    uint32_t o;
    asm("cvt.rna.tf32.f32 %0, %1;" : "=r"(o) : "f"(v));
    return o;
}
__device__ __forceinline__ float tf32f(float v) {
    return __uint_as_float(f2tf32(v));
}
__device__ __forceinline__ uint32_t smem_u32(const void* p) {
    uint32_t a;
    asm("{ .reg .u64 t; cvta.to.shared.u64 t, %1; cvt.u32.u64 %0, t; }"
        : "=r"(a) : "l"(p));
    return a;
}
__device__ __forceinline__ void cp16(uint32_t dst, const void* src) {
    asm volatile("cp.async.ca.shared.global [%0], [%1], 16;" :: "r"(dst), "l"(src));
}

// ---------------------------------------------------------------------------
// m -> tf32 bits
// ---------------------------------------------------------------------------
__global__ __launch_bounds__(256) void cvt_k(const float* __restrict__ s,
                                             float* __restrict__ d)
{
    int i = (blockIdx.x * 256 + threadIdx.x) * 4;
    float4 v = *(const float4*)&s[i];
    v.x = tf32f(v.x); v.y = tf32f(v.y); v.z = tf32f(v.z); v.w = tf32f(v.w);
    *(float4*)&d[i] = v;
}

// ---------------------------------------------------------------------------
// Weight transpose (+tf32 round): Wt[n*K + k] = tf32(W[k*N + n])
// ---------------------------------------------------------------------------
__global__ void transpose_k(const float* __restrict__ W, float* __restrict__ Wt,
                            int K, int N)
{
    __shared__ float tile[32][33];
    int kb = blockIdx.y * 32, nb = blockIdx.x * 32;
    int tx = threadIdx.x, ty = threadIdx.y;
#pragma unroll
    for (int i = 0; i < 32; i += 8)
        tile[ty + i][tx] = W[(size_t)(kb + ty + i) * N + nb + tx];
    __syncthreads();
#pragma unroll
    for (int i = 0; i < 32; i += 8)
        Wt[(size_t)(nb + ty + i) * K + kb + tx] = tf32f(tile[tx][ty + i]);
}

// ---------------------------------------------------------------------------
// tf32 tensor-core GEMM, cp.async double-buffered. Inputs pre-rounded to tf32.
// Block 128x128, BK=16, 8 warps (4x2), warp 32x64.
// ---------------------------------------------------------------------------
__global__ __launch_bounds__(256) void gemm_tc(
    const float* __restrict__ X, int ldx,
    const float* __restrict__ Wt,
    const float* __restrict__ bias,
    float* __restrict__ C, int ldc,
    int K, float alpha, float beta)
{
    __shared__ float As[2][2560];   // [buf][128*20]
    __shared__ float Bs[2][2560];

    const int t    = threadIdx.x;
    const int lane = t & 31;
    const int wid  = t >> 5;
    const int wm   = (wid & 3) * 32;
    const int wn   = (wid >> 2) * 64;
    const int row0 = blockIdx.y * 128;
    const int col0 = blockIdx.x * 128;
    const int lr = t >> 2;
    const int lc = (t & 3) * 4;
    const uint32_t asu = smem_u32(As);
    const uint32_t bsu = smem_u32(Bs);

    float acc[2][8][4];
#pragma unroll
    for (int mt = 0; mt < 2; mt++)
#pragma unroll
        for (int nt = 0; nt < 8; nt++)
#pragma unroll
            for (int i = 0; i < 4; i++) acc[mt][nt][i] = 0.f;

    auto issue = [&](int k0, int buf) {
#pragma unroll
        for (int half = 0; half < 2; half++) {
            int r = lr + half * 64;
            cp16(asu + (uint32_t)(buf * 2560 + r * 20 + lc) * 4,
                 &X[(size_t)(row0 + r) * ldx + k0 + lc]);
            cp16(bsu + (uint32_t)(buf * 2560 + r * 20 + lc) * 4,
                 &Wt[(size_t)(col0 + r) * K + k0 + lc]);
        }
        asm volatile("cp.async.commit_group;");
    };

    const int ntile = K >> 4;
    issue(0, 0);
    for (int i = 0; i < ntile; i++) {
        if (i + 1 < ntile) {
            issue((i + 1) << 4, (i + 1) & 1);
            asm volatile("cp.async.wait_group 1;");
        } else {
            asm volatile("cp.async.wait_group 0;");
        }
        __syncthreads();
        const float* A = As[i & 1];
        const float* B = Bs[i & 1];
#pragma unroll
        for (int ks = 0; ks < 16; ks += 8) {
            uint32_t af[2][4];
            const int fr = lane >> 2;
            const int fc = ks + (lane & 3);
#pragma unroll
            for (int mt = 0; mt < 2; mt++) {
                int r = wm + mt * 16 + fr;
                af[mt][0] = __float_as_uint(A[r * 20 + fc]);
                af[mt][1] = __float_as_uint(A[(r + 8) * 20 + fc]);
                af[mt][2] = __float_as_uint(A[r * 20 + fc + 4]);
                af[mt][3] = __float_as_uint(A[(r + 8) * 20 + fc + 4]);
            }
#pragma unroll
            for (int nt = 0; nt < 8; nt++) {
                uint32_t bf[2];
                int n = wn + nt * 8 + fr;
                bf[0] = __float_as_uint(B[n * 20 + fc]);
                bf[1] = __float_as_uint(B[n * 20 + fc + 4]);
                mma_tf32(acc[0][nt], af[0], bf);
                mma_tf32(acc[1][nt], af[1], bf);
            }
        }
        __syncthreads();
    }

#pragma unroll
    for (int mt = 0; mt < 2; mt++) {
#pragma unroll
        for (int nt = 0; nt < 8; nt++) {
            int rg = row0 + wm + mt * 16 + (lane >> 2);
            int cg = col0 + wn + nt * 8 + (lane & 3) * 2;
            float bx = 0.f, by = 0.f;
            if (bias) { bx = bias[cg]; by = bias[cg + 1]; }
#pragma unroll
            for (int half = 0; half < 2; half++) {
                int r = rg + half * 8;
                float vx = alpha * (acc[mt][nt][half * 2 + 0] + bx);
                float vy = alpha * (acc[mt][nt][half * 2 + 1] + by);
                float2* cp = (float2*)&C[(size_t)r * ldc + cg];
                if (beta != 0.f) {
                    float2 o = *cp;
                    vx += beta * o.x; vy += beta * o.y;
                }
                float2 v = {vx, vy};
                *cp = v;
            }
        }
    }
}

// ---------------------------------------------------------------------------
// Tensor-core column attention. One block per (l,h). 256 threads = 8 warps,
// each warp owns 16 query rows x all 128 key cols.
// Dynamic SMEM: Qs[128*68] | Ks[128*68] (P[128*132] overlaps Qs+Ks) | Vt[64*132]
// ---------------------------------------------------------------------------
__global__ __launch_bounds__(256, 2) void col_attn_tc(
    const float* __restrict__ Q, const float* __restrict__ K,
    const float* __restrict__ V, float* __restrict__ CW)
{
    extern __shared__ float sm[];
    float* Qs = sm;                    // [128][68]
    float* Ks = sm + 128 * 68;         // [128][68]
    float* P  = sm;                    // [128][132] (overlap, used after S)
    float* Vt = sm + 2 * 128 * 68;     // [64][132]

    const int l = blockIdx.x >> 3;
    const int h = blockIdx.x & 7;
    const int t = threadIdx.x;
    const int lane = t & 31;
    const int wid  = t >> 5;
    const int wm   = wid * 16;
    const int fr   = lane >> 2;
    const int q2   = (lane & 3) * 2;
    const size_t RS = (size_t)LL * INNERD;

    const float* qb = Q + (size_t)l * INNERD + h * DHEAD;
    const float* kb = K + (size_t)l * INNERD + h * DHEAD;
    const float* vb = V + (size_t)l * INNERD + h * DHEAD;

    // stage Q, K (tf32 bits)
    for (int idx = t; idx < 2048; idx += 256) {
        int row = idx >> 4, c4 = (idx & 15) * 4;
        float4 a = *(const float4*)(qb + row * RS + c4);
        float4 b = *(const float4*)(kb + row * RS + c4);
        a.x = tf32f(a.x); a.y = tf32f(a.y); a.z = tf32f(a.z); a.w = tf32f(a.w);
        b.x = tf32f(b.x); b.y = tf32f(b.y); b.z = tf32f(b.z); b.w = tf32f(b.w);
        *(float4*)&Qs[row * 68 + c4] = a;
        *(float4*)&Ks[row * 68 + c4] = b;
    }
    __syncthreads();

    // S = Q K^T  (per-warp: 16 rows x 128 cols)
    float acc[16][4];
#pragma unroll
    for (int nt = 0; nt < 16; nt++)
#pragma unroll
        for (int i = 0; i < 4; i++) acc[nt][i] = 0.f;

#pragma unroll
    for (int ks = 0; ks < 64; ks += 8) {
        const int fc = ks + (lane & 3);
        uint32_t af[4];
        af[0] = __float_as_uint(Qs[(wm + fr) * 68 + fc]);
        af[1] = __float_as_uint(Qs[(wm + fr + 8) * 68 + fc]);
        af[2] = __float_as_uint(Qs[(wm + fr) * 68 + fc + 4]);
        af[3] = __float_as_uint(Qs[(wm + fr + 8) * 68 + fc + 4]);
#pragma unroll
        for (int nt = 0; nt < 16; nt++) {
            uint32_t bf[2];
            bf[0] = __float_as_uint(Ks[(nt * 8 + fr) * 68 + fc]);
            bf[1] = __float_as_uint(Ks[(nt * 8 + fr) * 68 + fc + 4]);
            mma_tf32(acc[nt], af, bf);
        }
    }

    // softmax over j (rows wm+fr and wm+fr+8), scale 0.125
    float mx0 = -1e30f, mx1 = -1e30f;
#pragma unroll
    for (int nt = 0; nt < 16; nt++) {
        mx0 = fmaxf(mx0, fmaxf(acc[nt][0], acc[nt][1]));
        mx1 = fmaxf(mx1, fmaxf(acc[nt][2], acc[nt][3]));
    }
    mx0 = fmaxf(mx0, __shfl_xor_sync(0xffffffffu, mx0, 1));
    mx0 = fmaxf(mx0, __shfl_xor_sync(0xffffffffu, mx0, 2));
    mx1 = fmaxf(mx1, __shfl_xor_sync(0xffffffffu, mx1, 1));
    mx1 = fmaxf(mx1, __shfl_xor_sync(0xffffffffu, mx1, 2));
    float s0 = 0.f, s1 = 0.f;
#pragma unroll
    for (int nt = 0; nt < 16; nt++) {
        acc[nt][0] = __expf(0.125f * (acc[nt][0] - mx0)); s0 += acc[nt][0];
        acc[nt][1] = __expf(0.125f * (acc[nt][1] - mx0)); s0 += acc[nt][1];
        acc[nt][2] = __expf(0.125f * (acc[nt][2] - mx1)); s1 += acc[nt][2];
        acc[nt][3] = __expf(0.125f * (acc[nt][3] - mx1)); s1 += acc[nt][3];
    }
    s0 += __shfl_xor_sync(0xffffffffu, s0, 1);
    s0 += __shfl_xor_sync(0xffffffffu, s0, 2);
    s1 += __shfl_xor_sync(0xffffffffu, s1, 1);
    s1 += __shfl_xor_sync(0xffffffffu, s1, 2);

    __syncthreads();   // Qs/Ks dead — P may overwrite

    // write P (tf32 bits)
#pragma unroll
    for (int nt = 0; nt < 16; nt++) {
        float2 p0 = {tf32f(acc[nt][0]), tf32f(acc[nt][1])};
        float2 p1 = {tf32f(acc[nt][2]), tf32f(acc[nt][3])};
        *(float2*)&P[(wm + fr) * 132 + nt * 8 + q2]     = p0;
        *(float2*)&P[(wm + fr + 8) * 132 + nt * 8 + q2] = p1;
    }
    // stage V transposed: Vt[d][j] (tf32 bits)
    for (int idx = t; idx < 2048; idx += 256) {
        int j = idx >> 4, c4 = (idx & 15) * 4;
        float4 v = *(const float4*)(vb + j * RS + c4);
        Vt[(c4 + 0) * 132 + j] = tf32f(v.x);
        Vt[(c4 + 1) * 132 + j] = tf32f(v.y);
        Vt[(c4 + 2) * 132 + j] = tf32f(v.z);
        Vt[(c4 + 3) * 132 + j] = tf32f(v.w);
    }
    __syncthreads();

    // O = P V  (per-warp: 16 rows x 64 d)
    float o[8][4];
#pragma unroll
    for (int nt = 0; nt < 8; nt++)
#pragma unroll
        for (int i = 0; i < 4; i++) o[nt][i] = 0.f;

#pragma unroll
    for (int ks = 0; ks < 128; ks += 8) {
        const int fc = ks + (lane & 3);
        uint32_t af[4];
        af[0] = __float_as_uint(P[(wm + fr) * 132 + fc]);
        af[1] = __float_as_uint(P[(wm + fr + 8) * 132 + fc]);
        af[2] = __float_as_uint(P[(wm + fr) * 132 + fc + 4]);
        af[3] = __float_as_uint(P[(wm + fr + 8) * 132 + fc + 4]);
#pragma unroll
        for (int nt = 0; nt < 8; nt++) {
            uint32_t bf[2];
            bf[0] = __float_as_uint(Vt[(nt * 8 + fr) * 132 + fc]);
            bf[1] = __float_as_uint(Vt[(nt * 8 + fr) * 132 + fc + 4]);
            mma_tf32(o[nt], af, bf);
        }
    }

    const float inv0 = 1.f / s0, inv1 = 1.f / s1;
    float* ow = CW + (size_t)l * INNERD + h * DHEAD;
#pragma unroll
    for (int nt = 0; nt < 8; nt++) {
        int cg = nt * 8 + q2;
        float2 v0 = {tf32f(o[nt][0] * inv0), tf32f(o[nt][1] * inv0)};
        float2 v1 = {tf32f(o[nt][2] * inv1), tf32f(o[nt][3] * inv1)};
        *(float2*)(ow + (size_t)(wm + fr) * RS + cg)     = v0;
        *(float2*)(ow + (size_t)(wm + fr + 8) * RS + cg) = v1;
    }
}

// ---------------------------------------------------------------------------
// dots_tc (unchanged from round 5)
// ---------------------------------------------------------------------------
__global__ __launch_bounds__(256) void dots_tc(
    const float* __restrict__ TIE,
    const float* __restrict__ QH, const float* __restrict__ KH,
    float* __restrict__ D1, float* __restrict__ D2)
{
    __shared__ float As[128 * 36];
    __shared__ float Bs[128 * 36];
    __shared__ float wv_s[8 * 128];

    const int t    = threadIdx.x;
    const int lane = t & 31;
    const int wid  = t >> 5;
    const int wm   = (wid & 3) * 32;
    const int wn   = (wid >> 2) * 64;
    const int i0 = blockIdx.y * 128;
    const int j0 = blockIdx.x * 128;
    const int h  = blockIdx.z & 7;
    const int rz = blockIdx.z >> 3;

    float acc[2][8][4];
#pragma unroll
    for (int mt = 0; mt < 2; mt++)
#pragma unroll
        for (int nt = 0; nt < 8; nt++)
#pragma unroll
            for (int i = 0; i < 4; i++) acc[mt][nt][i] = 0.f;

    for (int rb = rz * 64; rb < rz * 64 + 64; rb += 8) {
        __syncthreads();
#pragma unroll
        for (int i = 0; i < 4; i++) {
            int e = t + 256 * i;
            int rr = e >> 7, row = e & 127;
            wv_s[rr * 128 + row] = TIE[((size_t)(h * RR + rb + rr)) * LL + i0 + row];
        }
        __syncthreads();
        for (int rr = 0; rr < 8; rr++) {
            const int r = rb + rr;
            const float* qbase = &QH[((size_t)r * LL + i0) * INNERD + h * DHEAD];
            const float* kbase = &KH[((size_t)r * LL + j0) * INNERD + h * DHEAD];
#pragma unroll
            for (int seg = 0; seg < 2; seg++) {
                const int d0 = seg * 32;
#pragma unroll
                for (int i = 0; i < 4; i++) {
                    int idx = t + 256 * i;
                    int row = idx >> 3, c4 = (idx & 7) * 4;
                    float wv = wv_s[rr * 128 + row];
                    float4 va = *(const float4*)&qbase[(size_t)row * INNERD + d0 + c4];
                    float4 vb = *(const float4*)&kbase[(size_t)row * INNERD + d0 + c4];
                    uint4 ua, ub;
                    ua.x = f2tf32(va.x * wv); ua.y = f2tf32(va.y * wv);
                    ua.z = f2tf32(va.z * wv); ua.w = f2tf32(va.w * wv);
                    ub.x = f2tf32(vb.x); ub.y = f2tf32(vb.y);
                    ub.z = f2tf32(vb.z); ub.w = f2tf32(vb.w);
                    *(uint4*)&As[row * 36 + c4] = ua;
                    *(uint4*)&Bs[row * 36 + c4] = ub;
                }
                __syncthreads();
#pragma unroll
                for (int ks = 0; ks < 32; ks += 8) {
                    uint32_t af[2][4];
                    const int fr = lane >> 2;
                    const int fc = ks + (lane & 3);
#pragma unroll
                    for (int mt = 0; mt < 2; mt++) {
                        int rw = wm + mt * 16 + fr;
                        af[mt][0] = __float_as_uint(As[rw * 36 + fc]);
                        af[mt][1] = __float_as_uint(As[(rw + 8) * 36 + fc]);
                        af[mt][2] = __float_as_uint(As[rw * 36 + fc + 4]);
                        af[mt][3] = __float_as_uint(As[(rw + 8) * 36 + fc + 4]);
                    }
#pragma unroll
                    for (int nt = 0; nt < 8; nt++) {
                        uint32_t bf[2];
                        int n = wn + nt * 8 + fr;
                        bf[0] = __float_as_uint(Bs[n * 36 + fc]);
                        bf[1] = __float_as_uint(Bs[n * 36 + fc + 4]);
                        mma_tf32(acc[0][nt], af[0], bf);
                        mma_tf32(acc[1][nt], af[1], bf);
                    }
                }
                __syncthreads();
            }
        }
    }

    float* OUT = (rz ? D2 : D1) + (size_t)h * LL * LL;
#pragma unroll
    for (int mt = 0; mt < 2; mt++) {
#pragma unroll
        for (int nt = 0; nt < 8; nt++) {
            int rg = i0 + wm + mt * 16 + (lane >> 2);
            int cg = j0 + wn + nt * 8 + (lane & 3) * 2;
#pragma unroll
            for (int half = 0; half < 2; half++) {
                int rw = rg + half * 8;
                float2 v = {0.125f * acc[mt][nt][half * 2 + 0],
                            0.125f * acc[mt][nt][half * 2 + 1]};
                *(float2*)&OUT[(size_t)rw * LL + cg] = v;
            }
        }
    }
}

// ---------------------------------------------------------------------------
// oh_tc (round 5 + tf32-rounded CH stores)
// ---------------------------------------------------------------------------
__global__ __launch_bounds__(256) void oh_tc(
    const float* __restrict__ ATT, const float* __restrict__ VH,
    float* __restrict__ CH)
{
    __shared__ float As[128 * 20];
    __shared__ float Bs[64 * 20];

    const int t    = threadIdx.x;
    const int lane = t & 31;
    const int wid  = t >> 5;
    const int wm   = (wid & 3) * 32;
    const int wn   = (wid >> 2) * 32;
    const int i0 = blockIdx.x * 128;
    const int r  = blockIdx.y >> 3;
    const int h  = blockIdx.y & 7;

    float acc[2][4][4];
#pragma unroll
    for (int mt = 0; mt < 2; mt++)
#pragma unroll
        for (int nt = 0; nt < 4; nt++)
#pragma unroll
            for (int i = 0; i < 4; i++) acc[mt][nt][i] = 0.f;

    for (int k0 = 0; k0 < LL; k0 += 16) {
#pragma unroll
        for (int i = 0; i < 2; i++) {
            int idx = t + 256 * i;
            int row = idx >> 2, c4 = (idx & 3) * 4;
            float4 va = *(const float4*)&ATT[((size_t)h * LL + i0 + row) * LL + k0 + c4];
            uint4 ua;
            ua.x = f2tf32(va.x); ua.y = f2tf32(va.y);
            ua.z = f2tf32(va.z); ua.w = f2tf32(va.w);
            *(uint4*)&As[row * 20 + c4] = ua;
        }
        {
            int kr = t >> 4;
            int dc = (t & 15) * 4;
            float4 vb = *(const float4*)&VH[((size_t)(r * LL + k0 + kr)) * INNERD + h * DHEAD + dc];
            Bs[(dc + 0) * 20 + kr] = tf32f(vb.x);
            Bs[(dc + 1) * 20 + kr] = tf32f(vb.y);
            Bs[(dc + 2) * 20 + kr] = tf32f(vb.z);
            Bs[(dc + 3) * 20 + kr] = tf32f(vb.w);
        }
        __syncthreads();
#pragma unroll
        for (int ks = 0; ks < 16; ks += 8) {
            uint32_t af[2][4];
            const int fr = lane >> 2;
            const int fc = ks + (lane & 3);
#pragma unroll
            for (int mt = 0; mt < 2; mt++) {
                int rw = wm + mt * 16 + fr;
                af[mt][0] = __float_as_uint(As[rw * 20 + fc]);
                af[mt][1] = __float_as_uint(As[(rw + 8) * 20 + fc]);
                af[mt][2] = __float_as_uint(As[rw * 20 + fc + 4]);
                af[mt][3] = __float_as_uint(As[(rw + 8) * 20 + fc + 4]);
            }
#pragma unroll
            for (int nt = 0; nt < 4; nt++) {
                uint32_t bf[2];
                int n = wn + nt * 8 + fr;
                bf[0] = __float_as_uint(Bs[n * 20 + fc]);
                bf[1] = __float_as_uint(Bs[n * 20 + fc + 4]);
                mma_tf32(acc[0][nt], af[0], bf);
                mma_tf32(acc[1][nt], af[1], bf);
            }
        }
        __syncthreads();
    }

#pragma unroll
    for (int mt = 0; mt < 2; mt++) {
#pragma unroll
        for (int nt = 0; nt < 4; nt++) {
            int rloc = i0 + wm + mt * 16 + (lane >> 2);
            int cg   = wn + nt * 8 + (lane & 3) * 2;
#pragma unroll
            for (int half = 0; half < 2; half++) {
                int rw = rloc + half * 8;
                float2 v = {tf32f(acc[mt][nt][half * 2 + 0]),
                            tf32f(acc[mt][nt][half * 2 + 1])};
                *(float2*)&CH[((size_t)(r * LL + rw)) * INNERD + h * DHEAD + cg] = v;
            }
        }
    }
}

// ---------------------------------------------------------------------------
// Row-tie weights -> TIE[h][r][l]
// ---------------------------------------------------------------------------
__global__ __launch_bounds__(128) void tie_k(
    const float* __restrict__ QS, const float* __restrict__ KS,
    float* __restrict__ TIE)
{
    const int l = blockIdx.x >> 3;
    const int h = blockIdx.x & 7;
    const int r = threadIdx.x;
    const float* q = &QS[l * DDIM + h * DHW];
    const float* k = &KS[((size_t)r * LL + l) * DDIM + h * DHW];
    float s = 0.f;
#pragma unroll
    for (int d = 0; d < DHW; d++) s += q[d] * k[d];
    s *= 0.25f;

    __shared__ float red[128];
    red[r] = s; __syncthreads();
    for (int o = 64; o; o >>= 1) { if (r < o) red[r] = fmaxf(red[r], red[r + o]); __syncthreads(); }
    float m = red[0]; __syncthreads();
    float e = __expf(s - m);
    red[r] = e; __syncthreads();
    for (int o = 64; o; o >>= 1) { if (r < o) red[r] += red[r + o]; __syncthreads(); }
    TIE[((size_t)h * RR + r) * LL + l] = e / red[0];
}

// ---------------------------------------------------------------------------
// Pair bias
// ---------------------------------------------------------------------------
__global__ __launch_bounds__(128) void pb_k(
    const float* __restrict__ pair, const float* __restrict__ gam,
    const float* __restrict__ bet, const float* __restrict__ Wp,
    float* __restrict__ PB)
{
    const int w    = threadIdx.x >> 5;
    const int lane = threadIdx.x & 31;
    const int pid  = blockIdx.x * 4 + w;
    float4 x4 = *(const float4*)&pair[(size_t)pid * DPAIR + lane * 4];
    float x[4] = {x4.x, x4.y, x4.z, x4.w};
    float s1 = x[0] + x[1] + x[2] + x[3];
    float s2 = x[0]*x[0] + x[1]*x[1] + x[2]*x[2] + x[3]*x[3];
#pragma unroll
    for (int o = 16; o; o >>= 1) {
        s1 += __shfl_xor_sync(0xffffffffu, s1, o);
        s2 += __shfl_xor_sync(0xffffffffu, s2, o);
    }
    float mu  = s1 * (1.f / DPAIR);
    float var = s2 * (1.f / DPAIR) - mu * mu;
    float inv = rsqrtf(var + 1e-5f);

    float acc[8];
#pragma unroll
    for (int hh = 0; hh < 8; hh++) acc[hh] = 0.f;
#pragma unroll
    for (int u = 0; u < 4; u++) {
        int c = lane * 4 + u;
        float nx = (x[u] - mu) * inv * gam[c] + bet[c];
#pragma unroll
        for (int hh = 0; hh < 8; hh++) acc[hh] += nx * Wp[c * 8 + hh];
    }
#pragma unroll
    for (int o = 16; o; o >>= 1)
#pragma unroll
        for (int hh = 0; hh < 8; hh++) acc[hh] += __shfl_xor_sync(0xffffffffu, acc[hh], o);
    if (lane == 0) {
#pragma unroll
        for (int hh = 0; hh < 8; hh++) PB[(size_t)pid * 8 + hh] = acc[hh];
    }
}

// ---------------------------------------------------------------------------
// softmax over dots1+dots2+pair bias
// ---------------------------------------------------------------------------
__global__ __launch_bounds__(128) void softh_k(
    const float* __restrict__ D1, const float* __restrict__ D2,
    const float* __restrict__ PB, float* __restrict__ ATT)
{
    const int i = blockIdx.x;
    const int h = blockIdx.y;
    const int t = threadIdx.x;
    const float* dp1 = &D1[((size_t)h * LL + i) * LL];
    const float* dp2 = &D2[((size_t)h * LL + i) * LL];
    float x[3];
#pragma unroll
    for (int u = 0; u < 3; u++) {
        int j = t + u * 128;
        x[u] = dp1[j] + dp2[j] + PB[((size_t)i * LL + j) * 8 + h];
    }
    __shared__ float red[128];
    float lm = fmaxf(fmaxf(x[0], x[1]), x[2]);
    red[t] = lm; __syncthreads();
    for (int o = 64; o; o >>= 1) { if (t < o) red[t] = fmaxf(red[t], red[t + o]); __syncthreads(); }
    float mx = red[0]; __syncthreads();
    float e[3], ls = 0.f;
#pragma unroll
    for (int u = 0; u < 3; u++) { e[u] = __expf(x[u] - mx); ls += e[u]; }
    red[t] = ls; __syncthreads();
    for (int o = 64; o; o >>= 1) { if (t < o) red[t] += red[t + o]; __syncthreads(); }
    float inv = 1.f / red[0];
    float* ap = &ATT[((size_t)h * LL + i) * LL];
#pragma unroll
    for (int u = 0; u < 3; u++) ap[t + u * 128] = e[u] * inv;
}

// ---------------------------------------------------------------------------
static float* sym(const void* s) {
    void* p = nullptr;
    cudaGetSymbolAddress(&p, s);
    return (float*)p;
}

extern "C" void kernel_launch(void* const* d_in, const int* in_sizes, int n_in,
                              void* d_out, int out_size)
{
    const float* m     = (const float*)d_in[0];
    const float* pair  = (const float*)d_in[1];
    const float* Wq_w  = (const float*)d_in[2];
    const float* Wkv_w = (const float*)d_in[3];
    const float* Wo_w  = (const float*)d_in[4];
    const float* bo_w  = (const float*)d_in[5];
    const float* Wq_h  = (const float*)d_in[6];
    const float* Wkv_h = (const float*)d_in[7];
    const float* Wo_h  = (const float*)d_in[8];
    const float* bo_h  = (const float*)d_in[9];
    const float* ln_g  = (const float*)d_in[10];
    const float* ln_b  = (const float*)d_in[11];
    const float* Wpair = (const float*)d_in[12];
    const float* Wsq   = (const float*)d_in[13];
    const float* bsq   = (const float*)d_in[14];
    const float* Wsk   = (const float*)d_in[15];
    const float* bsk   = (const float*)d_in[16];
    float* out = (float*)d_out;

    float* Mt    = sym(g_Mt);
    float* Q     = sym(g_Q);
    float* K     = sym(g_K);
    float* V     = sym(g_V);
    float* CW    = sym(g_CW);
    float* CH    = sym(g_CH);
    float* KS    = sym(g_KS);
    float* QS    = sym(g_QS);
    float* TIE   = sym(g_TIE);
    float* DOTS  = sym(g_DOTS);
    float* DOTS2 = sym(g_DOTS2);
    float* PB    = sym(g_PB);
    float* ATT   = sym(g_ATT);
    float* WtQw  = sym(g_WtQw);
    float* WtKVw = sym(g_WtKVw);
    float* WtOw  = sym(g_WtOw);
    float* WtQh  = sym(g_WtQh);
    float* WtKVh = sym(g_WtKVh);
    float* WtOh  = sym(g_WtOh);
    float* WtSq  = sym(g_WtSq);
    float* WtSk  = sym(g_WtSk);

    // enable 103KB dynamic smem for col_attn_tc (idempotent)
    static int attr_set = 0;
    const int CA_SMEM = (2 * 128 * 68 + 64 * 132) * 4;
    cudaFuncSetAttribute(col_attn_tc, cudaFuncAttributeMaxDynamicSharedMemorySize, CA_SMEM);

    const dim3 tb(32, 8);
    cvt_k<<<ML * DDIM / 1024, 256>>>(m, Mt);
    transpose_k<<<dim3(16, 4), tb>>>(Wq_w,  WtQw,  DDIM,   INNERD);
    transpose_k<<<dim3(32, 4), tb>>>(Wkv_w, WtKVw, DDIM,   2 * INNERD);
    transpose_k<<<dim3(4, 16), tb>>>(Wo_w,  WtOw,  INNERD, DDIM);
    transpose_k<<<dim3(16, 4), tb>>>(Wq_h,  WtQh,  DDIM,   INNERD);
    transpose_k<<<dim3(32, 4), tb>>>(Wkv_h, WtKVh, DDIM,   2 * INNERD);
    transpose_k<<<dim3(4, 16), tb>>>(Wo_h,  WtOh,  INNERD, DDIM);
    transpose_k<<<dim3(4, 4),  tb>>>(Wsq,   WtSq,  DDIM,   DDIM);
    transpose_k<<<dim3(4, 4),  tb>>>(Wsk,   WtSk,  DDIM,   DDIM);

    const dim3 gBig(4, 384);
    const dim3 gD  (1, 384);

    // ---- width (column) attention ----
    gemm_tc<<<gBig, 256>>>(Mt, DDIM, WtQw,               nullptr, Q, INNERD, DDIM, 1.f, 0.f);
    gemm_tc<<<gBig, 256>>>(Mt, DDIM, WtKVw,              nullptr, K, INNERD, DDIM, 1.f, 0.f);
    gemm_tc<<<gBig, 256>>>(Mt, DDIM, WtKVw + 512 * DDIM, nullptr, V, INNERD, DDIM, 1.f, 0.f);
    col_attn_tc<<<LL * HHEADS, 256, CA_SMEM>>>(Q, K, V, CW);

    // ---- height (row) attention ----
    gemm_tc<<<gBig, 256>>>(Mt, DDIM, WtQh,               nullptr, Q, INNERD, DDIM, 1.f, 0.f);
    gemm_tc<<<gBig, 256>>>(Mt, DDIM, WtKVh,              nullptr, K, INNERD, DDIM, 1.f, 0.f);
    gemm_tc<<<gBig, 256>>>(Mt, DDIM, WtKVh + 512 * DDIM, nullptr, V, INNERD, DDIM, 1.f, 0.f);

    gemm_tc<<<dim3(1, 3), 256>>>(Mt, DDIM, WtSq, bsq, QS, DDIM, DDIM, 1.f, 0.f);
    gemm_tc<<<gD, 256>>>(Mt, DDIM, WtSk, bsk, KS, DDIM, DDIM, 1.f, 0.f);

    tie_k<<<LL * HHEADS, 128>>>(QS, KS, TIE);
    dots_tc<<<dim3(3, 3, 16), 256>>>(TIE, Q, K, DOTS, DOTS2);
    pb_k<<<LL * LL / 4, 128>>>(pair, ln_g, ln_b, Wpair, PB);
    softh_k<<<dim3(LL, HHEADS), 128>>>(DOTS, DOTS2, PB, ATT);
    oh_tc<<<dim3(3, RR * HHEADS), 256>>>(ATT, V, CH);

    // ---- fused output ----
    gemm_tc<<<gD, 256>>>(CW, INNERD, WtOw, bo_w, out, DDIM, INNERD, 0.5f, 0.f);
    gemm_tc<<<gD, 256>>>(CH, INNERD, WtOh, bo_h, out, DDIM, INNERD, 0.5f, 1.f);
}